// round 1
// baseline (speedup 1.0000x reference)
#include <cuda_runtime.h>
#include <math.h>

// ---------------------------------------------------------------------------
// Problem constants
// ---------------------------------------------------------------------------
#define BN 2
#define TN 1024
#define CN 768
#define HN 12
#define HDN 64
#define LN 4
#define DIN 64
#define VN 50304
#define CFN 3072          // 4*C
#define MN (BN*TN)        // 2048 rows

// ---------------------------------------------------------------------------
// Scratch (static device globals; allocation APIs are forbidden)
// ---------------------------------------------------------------------------
__device__ float g_x[MN*CN];
__device__ float g_h[MN*CN];
__device__ float g_qkv[MN*3*CN];
__device__ float g_y[MN*CN];
__device__ float g_qi[MN*DIN];
__device__ float g_ki[MN*DIN];
__device__ float g_p[BN*TN*TN];     // rawT then pT, layout [b][k][q]
__device__ float g_mask[BN*TN*TN];  // accumulated attn_mask, layout [b][q][k] (k<=q valid)
__device__ float g_fc[MN*CFN];

// ---------------------------------------------------------------------------
// Embedding: x = wte[idx] + wpe[:T]
// ---------------------------------------------------------------------------
__global__ void k_embed(const float* __restrict__ wte, const float* __restrict__ wpe,
                        const int* __restrict__ idx, float* __restrict__ x) {
    int i = blockIdx.x * blockDim.x + threadIdx.x;
    if (i >= MN*CN) return;
    int c = i % CN;
    int bt = i / CN;
    int t = bt % TN;
    x[i] = wte[(size_t)idx[bt]*CN + c] + wpe[t*CN + c];
}

__global__ void k_zero(float* __restrict__ p, int n) {
    int i = blockIdx.x * blockDim.x + threadIdx.x;
    for (; i < n; i += gridDim.x * blockDim.x) p[i] = 0.0f;
}

// ---------------------------------------------------------------------------
// LayerNorm (block per row, C = 768 = 3*256)
// ---------------------------------------------------------------------------
__global__ void k_ln(const float* __restrict__ x, const float* __restrict__ w,
                     const float* __restrict__ b, float* __restrict__ o) {
    int row = blockIdx.x;
    const float* xr = x + (size_t)row*CN;
    float* orow = o + (size_t)row*CN;
    __shared__ float red[256];
    int t = threadIdx.x;
    float lx0 = xr[t], lx1 = xr[t+256], lx2 = xr[t+512];
    red[t] = lx0 + lx1 + lx2;
    __syncthreads();
    for (int st = 128; st > 0; st >>= 1) {
        if (t < st) red[t] += red[t+st];
        __syncthreads();
    }
    float mu = red[0] / (float)CN;
    __syncthreads();
    float d0 = lx0-mu, d1 = lx1-mu, d2 = lx2-mu;
    red[t] = d0*d0 + d1*d1 + d2*d2;
    __syncthreads();
    for (int st = 128; st > 0; st >>= 1) {
        if (t < st) red[t] += red[t+st];
        __syncthreads();
    }
    float var = red[0] / (float)CN;
    float inv = 1.0f / sqrtf(var + 1e-5f);
    orow[t]     = d0*inv*w[t]     + b[t];
    orow[t+256] = d1*inv*w[t+256] + b[t+256];
    orow[t+512] = d2*inv*w[t+512] + b[t+512];
}

// ---------------------------------------------------------------------------
// GEMM: O[m,n] = sum_k A[m,k]*W[n,k] (+bias[n]) (+res[m,n])
// A:[M,K] row-major, W:[N,K] row-major. M%64==0, N%64==0, K%16==0.
// 64x64 tile, 16x16 threads, 4x4 per thread.
// ---------------------------------------------------------------------------
__global__ void k_gemm(const float* __restrict__ A, const float* __restrict__ W,
                       const float* __restrict__ bias, const float* __restrict__ res,
                       float* __restrict__ O, int M, int N, int K) {
    __shared__ float As[16][64];
    __shared__ float Ws[16][64];
    int tx = threadIdx.x, ty = threadIdx.y;
    int tid = ty*16 + tx;
    int m0 = blockIdx.y*64, n0 = blockIdx.x*64;
    int lr = tid >> 2;          // 0..63
    int lk = (tid & 3) * 4;     // 0,4,8,12
    const float* Ap = A + (size_t)(m0 + lr)*K + lk;
    const float* Wp = W + (size_t)(n0 + lr)*K + lk;

    float acc[4][4];
#pragma unroll
    for (int i = 0; i < 4; i++)
#pragma unroll
        for (int j = 0; j < 4; j++) acc[i][j] = 0.0f;

    for (int k0 = 0; k0 < K; k0 += 16) {
        float4 av = *(const float4*)(Ap + k0);
        float4 wv = *(const float4*)(Wp + k0);
        __syncthreads();
        As[lk+0][lr] = av.x; As[lk+1][lr] = av.y; As[lk+2][lr] = av.z; As[lk+3][lr] = av.w;
        Ws[lk+0][lr] = wv.x; Ws[lk+1][lr] = wv.y; Ws[lk+2][lr] = wv.z; Ws[lk+3][lr] = wv.w;
        __syncthreads();
#pragma unroll
        for (int kk = 0; kk < 16; ++kk) {
            float4 a4 = *(const float4*)(&As[kk][ty*4]);
            float4 w4 = *(const float4*)(&Ws[kk][tx*4]);
            float av_[4] = {a4.x, a4.y, a4.z, a4.w};
            float wv_[4] = {w4.x, w4.y, w4.z, w4.w};
#pragma unroll
            for (int i = 0; i < 4; i++)
#pragma unroll
                for (int j = 0; j < 4; j++)
                    acc[i][j] += av_[i]*wv_[j];
        }
    }

#pragma unroll
    for (int i = 0; i < 4; i++) {
        int m = m0 + ty*4 + i;
#pragma unroll
        for (int j = 0; j < 4; j++) {
            int n = n0 + tx*4 + j;
            float v = acc[i][j];
            if (bias) v += bias[n];
            if (res)  v += res[(size_t)m*N + n];
            O[(size_t)m*N + n] = v;
        }
    }
}

// ---------------------------------------------------------------------------
// entmax (alpha = 1.000001) over the 2-vector [r, 0], bisection, f32-faithful.
// pow(x, 1e6) emulated as expf(1e6*log1p(x-1)) with exact FMA residual split.
// In place on g_p (raw -> p), layout [b][k][q]; only q>k entries computed.
// ---------------------------------------------------------------------------
__device__ __forceinline__ float pw1e6(float base) {
    float t = base - 1.0f;                 // exact (base in (0.999, 1.0])
    float u = 1.0e6f * t;
    float e = fmaf(1.0e6f, t, -u);         // exact product residual
    // 1e6*log1p(t) = u + e + 1e6*(-t^2/2 + t^3/3 - t^4/4)
    float c = fmaf(u*t, fmaf(t, fmaf(-0.25f, t, 0.33333333333333333f), -0.5f), e);
    return expf(u) * (1.0f + c*(1.0f + 0.5f*c));
}

__global__ void k_entmax(float* __restrict__ pT, const float* __restrict__ int_bias,
                         int l, float am1f, float halfpow) {
    long long i = (long long)blockIdx.x * blockDim.x + threadIdx.x;
    if (i >= (long long)BN*TN*TN) return;
    int q = (int)(i % TN);
    int k = (int)((i / TN) % TN);
    if (q <= k) return;

    float r   = pT[i]*0.125f + int_bias[l];
    float Xs0 = r * am1f;                       // Xs1 = 0
    float maxv = fmaxf(Xs0, 0.0f);
    float tau_lo = maxv - 1.0f;
    float tau_hi = maxv - halfpow;
    float dm = tau_hi - tau_lo;
    float f_lo = (pw1e6(fmaxf(Xs0 - tau_lo, 0.0f)) + pw1e6(fmaxf(-tau_lo, 0.0f))) - 1.0f;

    float p0 = 0.0f, p1 = 0.0f;
#pragma unroll 1
    for (int it = 0; it < 50; ++it) {
        dm *= 0.5f;
        float tm = tau_lo + dm;
        p0 = pw1e6(fmaxf(Xs0 - tm, 0.0f));
        p1 = pw1e6(fmaxf(-tm, 0.0f));
        float fm = (p0 + p1) - 1.0f;
        bool take = (fm * f_lo >= 0.0f);
        if (tm == tau_lo) break;               // f32-converged: all later iters identical
        if (take) tau_lo = tm;
    }
    pT[i] = p0 / (p0 + p1);
}

// ---------------------------------------------------------------------------
// cumprod over queries per (b,k) column + mask accumulation:
//   mask[b][q][k] += log(cumprod_{q'<=q} p + 1e-40)   (q>k; q==k adds log(1)=0)
// ---------------------------------------------------------------------------
__global__ void k_mask(const float* __restrict__ pT, float* __restrict__ mask) {
    int col = blockIdx.x * blockDim.x + threadIdx.x;
    if (col >= BN*TN) return;
    int b = col >> 10, k = col & (TN-1);
    const float* pr = pT + ((size_t)b*TN + k)*TN;
    float* mcol = mask + (size_t)b*TN*TN + k;
    float c = 1.0f;
#pragma unroll 4
    for (int q = k+1; q < TN; ++q) {
        c = c * pr[q];
        mcol[(size_t)q*TN] += logf(c + 1e-40f);
    }
}

// ---------------------------------------------------------------------------
// Attention: one block per (q, h, b). Scores over k<=q, softmax, weighted V.
// ---------------------------------------------------------------------------
__global__ void k_attn(const float* __restrict__ qkv, const float* __restrict__ mask,
                       float* __restrict__ y) {
    int qi = blockIdx.x, h = blockIdx.y, b = blockIdx.z;
    int tid = threadIdx.x;   // 128
    __shared__ float qs[HDN];
    __shared__ float s[TN];
    __shared__ float red[128];

    const float* base = qkv + (size_t)(b*TN)*3*CN;
    const float* qrow = base + (size_t)qi*3*CN + h*HDN;
    if (tid < HDN) qs[tid] = qrow[tid];
    __syncthreads();

    const float* mrow = mask + ((size_t)(b*TN) + qi)*TN;
    float lmax = -INFINITY;
    for (int k = tid; k <= qi; k += 128) {
        const float* krow = base + (size_t)k*3*CN + CN + h*HDN;
        float dot = 0.0f;
#pragma unroll
        for (int d = 0; d < HDN; d += 4) {
            float4 kv4 = *(const float4*)(krow + d);
            dot += qs[d]*kv4.x + qs[d+1]*kv4.y + qs[d+2]*kv4.z + qs[d+3]*kv4.w;
        }
        float sc = dot*0.125f + mrow[k];
        s[k] = sc;
        lmax = fmaxf(lmax, sc);
    }
    red[tid] = lmax; __syncthreads();
    for (int st = 64; st > 0; st >>= 1) {
        if (tid < st) red[tid] = fmaxf(red[tid], red[tid+st]);
        __syncthreads();
    }
    float m = red[0];
    __syncthreads();

    float lsum = 0.0f;
    for (int k = tid; k <= qi; k += 128) {
        float e = expf(s[k] - m);
        s[k] = e;
        lsum += e;
    }
    red[tid] = lsum; __syncthreads();
    for (int st = 64; st > 0; st >>= 1) {
        if (tid < st) red[tid] += red[tid+st];
        __syncthreads();
    }
    float inv = 1.0f / red[0];
    __syncthreads();

    int d = tid & 63, part = tid >> 6;
    float acc = 0.0f;
    for (int k = part; k <= qi; k += 2)
        acc += s[k] * base[(size_t)k*3*CN + 2*CN + h*HDN + d];
    red[tid] = acc; __syncthreads();
    if (tid < 64) {
        float tot = (red[tid] + red[tid+64]) * inv;
        y[((size_t)(b*TN) + qi)*CN + h*HDN + d] = tot;
    }
}

// ---------------------------------------------------------------------------
// GELU (tanh approximation, matching reference constants)
// ---------------------------------------------------------------------------
__global__ void k_gelu(float* __restrict__ p, int n) {
    int i = blockIdx.x * blockDim.x + threadIdx.x;
    if (i >= n) return;
    float v = p[i];
    float inner = 0.7978845608028654f * (v + 0.044715f*v*v*v);
    p[i] = 0.5f*v*(1.0f + tanhf(inner));
}

// ---------------------------------------------------------------------------
// Host orchestration
// ---------------------------------------------------------------------------
extern "C" void kernel_launch(void* const* d_in, const int* in_sizes, int n_in,
                              void* d_out, int out_size) {
    const float* wte    = (const float*)d_in[0];
    const float* wpe    = (const float*)d_in[1];
    const float* ln1_w  = (const float*)d_in[2];
    const float* ln1_b  = (const float*)d_in[3];
    const float* attn_w = (const float*)d_in[4];
    const float* attn_b = (const float*)d_in[5];
    const float* qint_w = (const float*)d_in[6];
    const float* kint_w = (const float*)d_in[7];
    const float* int_bias = (const float*)d_in[8];
    const float* proj_w = (const float*)d_in[9];
    const float* proj_b = (const float*)d_in[10];
    const float* ln2_w  = (const float*)d_in[11];
    const float* ln2_b  = (const float*)d_in[12];
    const float* fc_w   = (const float*)d_in[13];
    const float* fc_b   = (const float*)d_in[14];
    const float* fc2_w  = (const float*)d_in[15];
    const float* fc2_b  = (const float*)d_in[16];
    const float* lnf_w  = (const float*)d_in[17];
    const float* lnf_b  = (const float*)d_in[18];
    const int*   idx    = (const int*)d_in[19];
    float* out = (float*)d_out;

    float *px, *ph, *pqkv, *py, *pqi, *pki, *pp, *pmask, *pfc;
    cudaGetSymbolAddress((void**)&px,    g_x);
    cudaGetSymbolAddress((void**)&ph,    g_h);
    cudaGetSymbolAddress((void**)&pqkv,  g_qkv);
    cudaGetSymbolAddress((void**)&py,    g_y);
    cudaGetSymbolAddress((void**)&pqi,   g_qi);
    cudaGetSymbolAddress((void**)&pki,   g_ki);
    cudaGetSymbolAddress((void**)&pp,    g_p);
    cudaGetSymbolAddress((void**)&pmask, g_mask);
    cudaGetSymbolAddress((void**)&pfc,   g_fc);

    // f32-faithful entmax constants (computed in double, as JAX weak scalars would)
    double am1d = 1.000001 - 1.0;
    float am1f = (float)am1d;
    float halfpow = (float)pow(0.5, am1d);

    dim3 tb(16, 16);

    k_embed<<<(MN*CN + 255)/256, 256>>>(wte, wpe, idx, px);
    k_zero<<<1024, 256>>>(pmask, BN*TN*TN);

    for (int l = 0; l < LN; ++l) {
        // --- attention sub-block ---
        k_ln<<<MN, 256>>>(px, ln1_w + l*CN, ln1_b + l*CN, ph);
        k_gemm<<<dim3(3*CN/64, MN/64), tb>>>(ph, attn_w + (size_t)l*3*CN*CN,
                                             attn_b + l*3*CN, nullptr, pqkv, MN, 3*CN, CN);
        k_gemm<<<dim3(DIN/64, MN/64), tb>>>(ph, qint_w + (size_t)l*DIN*CN,
                                            nullptr, nullptr, pqi, MN, DIN, CN);
        k_gemm<<<dim3(DIN/64, MN/64), tb>>>(ph, kint_w + (size_t)l*DIN*CN,
                                            nullptr, nullptr, pki, MN, DIN, CN);
        // rawT[b][k][q] = kint[b,k,:] . qint[b,q,:]
        for (int b = 0; b < BN; ++b)
            k_gemm<<<dim3(TN/64, TN/64), tb>>>(pki + (size_t)b*TN*DIN, pqi + (size_t)b*TN*DIN,
                                               nullptr, nullptr, pp + (size_t)b*TN*TN,
                                               TN, TN, DIN);
        k_entmax<<<(BN*TN*TN + 255)/256, 256>>>(pp, int_bias, l, am1f, halfpow);
        k_mask<<<(BN*TN + 127)/128, 128>>>(pp, pmask);
        k_attn<<<dim3(TN, HN, BN), 128>>>(pqkv, pmask, py);
        k_gemm<<<dim3(CN/64, MN/64), tb>>>(py, proj_w + (size_t)l*CN*CN,
                                           proj_b + l*CN, px, px, MN, CN, CN);
        // --- MLP sub-block ---
        k_ln<<<MN, 256>>>(px, ln2_w + l*CN, ln2_b + l*CN, ph);
        k_gemm<<<dim3(CFN/64, MN/64), tb>>>(ph, fc_w + (size_t)l*CFN*CN,
                                            fc_b + l*CFN, nullptr, pfc, MN, CFN, CN);
        k_gelu<<<(MN*CFN + 255)/256, 256>>>(pfc, MN*CFN);
        k_gemm<<<dim3(CN/64, MN/64), tb>>>(pfc, fc2_w + (size_t)l*CN*CFN,
                                           fc2_b + l*CN, px, px, MN, CN, CFN);
    }

    k_ln<<<MN, 256>>>(px, lnf_w, lnf_b, ph);
    k_gemm<<<dim3(VN/64, MN/64), tb>>>(ph, wte, nullptr, nullptr, out, MN, VN, CN);
}

// round 3
// speedup vs baseline: 1.2540x; 1.2540x over previous
#include <cuda_runtime.h>
#include <math.h>
#include <stdint.h>

// ---------------------------------------------------------------------------
// Problem constants
// ---------------------------------------------------------------------------
#define BN 2
#define TN 1024
#define CN 768
#define HN 12
#define HDN 64
#define LN 4
#define DIN 64
#define VN 50304
#define CFN 3072          // 4*C
#define MN (BN*TN)        // 2048 rows

// ---------------------------------------------------------------------------
// Scratch (static device globals; allocation APIs are forbidden)
// ---------------------------------------------------------------------------
__device__ float g_x[MN*CN];
__device__ float g_h[MN*CN];
__device__ float g_qkv[MN*3*CN];
__device__ float g_y[MN*CN];
__device__ float g_qi[MN*DIN];
__device__ float g_ki[MN*DIN];
__device__ float g_p[BN*TN*TN];     // rawT then pT, layout [b][k][q]
__device__ float g_mask[BN*TN*TN];  // accumulated attn_mask, layout [b][q][k]
__device__ float g_fc[MN*CFN];

// ---------------------------------------------------------------------------
// Embedding: x = wte[idx] + wpe[:T]
// ---------------------------------------------------------------------------
__global__ void k_embed(const float* __restrict__ wte, const float* __restrict__ wpe,
                        const int* __restrict__ idx, float* __restrict__ x) {
    int i = blockIdx.x * blockDim.x + threadIdx.x;
    if (i >= MN*CN) return;
    int c = i % CN;
    int bt = i / CN;
    int t = bt % TN;
    x[i] = wte[(size_t)idx[bt]*CN + c] + wpe[t*CN + c];
}

__global__ void k_zero(float* __restrict__ p, int n) {
    int i = blockIdx.x * blockDim.x + threadIdx.x;
    for (; i < n; i += gridDim.x * blockDim.x) p[i] = 0.0f;
}

// ---------------------------------------------------------------------------
// LayerNorm (block per row, C = 768 = 3*256)
// ---------------------------------------------------------------------------
__global__ void k_ln(const float* __restrict__ x, const float* __restrict__ w,
                     const float* __restrict__ b, float* __restrict__ o) {
    int row = blockIdx.x;
    const float* xr = x + (size_t)row*CN;
    float* orow = o + (size_t)row*CN;
    __shared__ float red[256];
    int t = threadIdx.x;
    float lx0 = xr[t], lx1 = xr[t+256], lx2 = xr[t+512];
    red[t] = lx0 + lx1 + lx2;
    __syncthreads();
    for (int st = 128; st > 0; st >>= 1) {
        if (t < st) red[t] += red[t+st];
        __syncthreads();
    }
    float mu = red[0] / (float)CN;
    __syncthreads();
    float d0 = lx0-mu, d1 = lx1-mu, d2 = lx2-mu;
    red[t] = d0*d0 + d1*d1 + d2*d2;
    __syncthreads();
    for (int st = 128; st > 0; st >>= 1) {
        if (t < st) red[t] += red[t+st];
        __syncthreads();
    }
    float var = red[0] / (float)CN;
    float inv = 1.0f / sqrtf(var + 1e-5f);
    orow[t]     = d0*inv*w[t]     + b[t];
    orow[t+256] = d1*inv*w[t+256] + b[t+256];
    orow[t+512] = d2*inv*w[t+512] + b[t+512];
}

// ---------------------------------------------------------------------------
// 3xTF32 tensor-core GEMM: O[m,n] = sum_k A[m,k]*W[n,k] (+bias[n]) (+res[m,n])
// A:[M,K] row-major, W:[N,K] row-major. M%128==0, N%64==0, K%16==0.
// Block tile 128x64, BK=16, 8 warps (4Mx2N), warp tile 32x32 (2x4 mma frags).
// hi/lo tf32 split -> 3 mma per fragment pair, fp32-class accuracy.
// Grid: x = M/128 (fastest, shares W tile in L2), y = N/64.
// ---------------------------------------------------------------------------
#define SAS 136   // smem A stride (==8 mod 32 -> conflict-free frag loads)
#define SBS 72    // smem B stride (==8 mod 32)
#define SWZ(k, x) ((x) ^ ((((k) >> 2) & 3) << 3))

__device__ __forceinline__ uint32_t tf32_rna(float v) {
    uint32_t r;
    asm("cvt.rna.tf32.f32 %0, %1;" : "=r"(r) : "f"(v));
    return r;
}

__device__ __forceinline__ void mma_tf32(float* d, const uint32_t* a, const uint32_t* b) {
    asm volatile(
        "mma.sync.aligned.m16n8k8.row.col.f32.tf32.tf32.f32 "
        "{%0,%1,%2,%3}, {%4,%5,%6,%7}, {%8,%9}, {%0,%1,%2,%3};"
        : "+f"(d[0]), "+f"(d[1]), "+f"(d[2]), "+f"(d[3])
        : "r"(a[0]), "r"(a[1]), "r"(a[2]), "r"(a[3]), "r"(b[0]), "r"(b[1]));
}

__global__ __launch_bounds__(256)
void k_gemm(const float* __restrict__ A, const float* __restrict__ W,
            const float* __restrict__ bias, const float* __restrict__ res,
            float* __restrict__ O, int M, int N, int K) {
    __shared__ uint32_t sAh[16*SAS], sAl[16*SAS];
    __shared__ uint32_t sBh[16*SBS], sBl[16*SBS];

    int tid = threadIdx.x;
    int lane = tid & 31, warp = tid >> 5;
    int wm = warp >> 1, wn = warp & 1;           // warp grid 4x2
    int m0 = blockIdx.x * 128, n0 = blockIdx.y * 64;

    int gr = tid >> 2;            // 0..63
    int gc = (tid & 3) * 4;       // 0,4,8,12
    const float* Ap0 = A + (size_t)(m0 + gr)*K + gc;
    const float* Ap1 = A + (size_t)(m0 + gr + 64)*K + gc;
    const float* Bp  = W + (size_t)(n0 + gr)*K + gc;

    float acc[2][4][4];
#pragma unroll
    for (int i = 0; i < 2; i++)
#pragma unroll
        for (int j = 0; j < 4; j++)
#pragma unroll
            for (int v = 0; v < 4; v++) acc[i][j][v] = 0.0f;

    float4 av0 = *(const float4*)Ap0;
    float4 av1 = *(const float4*)Ap1;
    float4 bv  = *(const float4*)Bp;

    int r = lane >> 2, c = lane & 3;

    for (int k0 = 0; k0 < K; k0 += 16) {
        __syncthreads();   // previous compute done before overwrite
        {
            float va0[4] = {av0.x, av0.y, av0.z, av0.w};
            float va1[4] = {av1.x, av1.y, av1.z, av1.w};
            float vb_[4] = {bv.x,  bv.y,  bv.z,  bv.w};
#pragma unroll
            for (int j = 0; j < 4; j++) {
                int kk = gc + j;
                uint32_t h0 = tf32_rna(va0[j]);
                sAh[kk*SAS + SWZ(kk, gr)]      = h0;
                sAl[kk*SAS + SWZ(kk, gr)]      = tf32_rna(va0[j] - __uint_as_float(h0));
                uint32_t h1 = tf32_rna(va1[j]);
                sAh[kk*SAS + SWZ(kk, gr + 64)] = h1;
                sAl[kk*SAS + SWZ(kk, gr + 64)] = tf32_rna(va1[j] - __uint_as_float(h1));
                uint32_t hb = tf32_rna(vb_[j]);
                sBh[kk*SBS + SWZ(kk, gr)]      = hb;
                sBl[kk*SBS + SWZ(kk, gr)]      = tf32_rna(vb_[j] - __uint_as_float(hb));
            }
        }
        __syncthreads();

        if (k0 + 16 < K) {          // prefetch next tile during compute
            Ap0 += 16; Ap1 += 16; Bp += 16;
            av0 = *(const float4*)Ap0;
            av1 = *(const float4*)Ap1;
            bv  = *(const float4*)Bp;
        }

#pragma unroll
        for (int kk8 = 0; kk8 < 16; kk8 += 8) {
            uint32_t ah[2][4], al[2][4], bh[4][2], bl[4][2];
            int kA0 = kk8 + c, kA1 = kk8 + c + 4;
#pragma unroll
            for (int mf = 0; mf < 2; mf++) {
                int mi = wm*32 + mf*16 + r;
                ah[mf][0] = sAh[kA0*SAS + SWZ(kA0, mi)];
                ah[mf][1] = sAh[kA0*SAS + SWZ(kA0, mi + 8)];
                ah[mf][2] = sAh[kA1*SAS + SWZ(kA1, mi)];
                ah[mf][3] = sAh[kA1*SAS + SWZ(kA1, mi + 8)];
                al[mf][0] = sAl[kA0*SAS + SWZ(kA0, mi)];
                al[mf][1] = sAl[kA0*SAS + SWZ(kA0, mi + 8)];
                al[mf][2] = sAl[kA1*SAS + SWZ(kA1, mi)];
                al[mf][3] = sAl[kA1*SAS + SWZ(kA1, mi + 8)];
            }
#pragma unroll
            for (int nf = 0; nf < 4; nf++) {
                int ni = wn*32 + nf*8 + r;
                bh[nf][0] = sBh[kA0*SBS + SWZ(kA0, ni)];
                bh[nf][1] = sBh[kA1*SBS + SWZ(kA1, ni)];
                bl[nf][0] = sBl[kA0*SBS + SWZ(kA0, ni)];
                bl[nf][1] = sBl[kA1*SBS + SWZ(kA1, ni)];
            }
#pragma unroll
            for (int mf = 0; mf < 2; mf++)
#pragma unroll
                for (int nf = 0; nf < 4; nf++) {
                    mma_tf32(acc[mf][nf], ah[mf], bh[nf]);
                    mma_tf32(acc[mf][nf], ah[mf], bl[nf]);
                    mma_tf32(acc[mf][nf], al[mf], bh[nf]);
                }
        }
    }

    // epilogue: c0:(r, 2c) c1:(r, 2c+1) c2:(r+8, 2c) c3:(r+8, 2c+1)
#pragma unroll
    for (int mf = 0; mf < 2; mf++) {
        int m = m0 + wm*32 + mf*16 + r;
#pragma unroll
        for (int nf = 0; nf < 4; nf++) {
            int n = n0 + wn*32 + nf*8 + c*2;
            float v0 = acc[mf][nf][0], v1 = acc[mf][nf][1];
            float v2 = acc[mf][nf][2], v3 = acc[mf][nf][3];
            if (bias) {
                float b0 = bias[n], b1 = bias[n+1];
                v0 += b0; v1 += b1; v2 += b0; v3 += b1;
            }
            if (res) {
                v0 += res[(size_t)m*N + n];
                v1 += res[(size_t)m*N + n + 1];
                v2 += res[(size_t)(m+8)*N + n];
                v3 += res[(size_t)(m+8)*N + n + 1];
            }
            O[(size_t)m*N + n]         = v0;
            O[(size_t)m*N + n + 1]     = v1;
            O[(size_t)(m+8)*N + n]     = v2;
            O[(size_t)(m+8)*N + n + 1] = v3;
        }
    }
}

// ---------------------------------------------------------------------------
// entmax (alpha = 1.000001) over the 2-vector [r, 0], bisection, f32-faithful.
// ---------------------------------------------------------------------------
__device__ __forceinline__ float pw1e6(float base) {
    float t = base - 1.0f;                 // exact (base in (0.999, 1.0])
    float u = 1.0e6f * t;
    float e = fmaf(1.0e6f, t, -u);         // exact product residual
    float c = fmaf(u*t, fmaf(t, fmaf(-0.25f, t, 0.33333333333333333f), -0.5f), e);
    return expf(u) * (1.0f + c*(1.0f + 0.5f*c));
}

__global__ void k_entmax(float* __restrict__ pT, const float* __restrict__ int_bias,
                         int l, float am1f, float halfpow) {
    long long i = (long long)blockIdx.x * blockDim.x + threadIdx.x;
    if (i >= (long long)BN*TN*TN) return;
    int q = (int)(i % TN);
    int k = (int)((i / TN) % TN);
    if (q <= k) return;

    float r   = pT[i]*0.125f + int_bias[l];
    float Xs0 = r * am1f;
    float maxv = fmaxf(Xs0, 0.0f);
    float tau_lo = maxv - 1.0f;
    float tau_hi = maxv - halfpow;
    float dm = tau_hi - tau_lo;
    float f_lo = (pw1e6(fmaxf(Xs0 - tau_lo, 0.0f)) + pw1e6(fmaxf(-tau_lo, 0.0f))) - 1.0f;

    float p0 = 0.0f, p1 = 0.0f;
#pragma unroll 1
    for (int it = 0; it < 50; ++it) {
        dm *= 0.5f;
        float tm = tau_lo + dm;
        p0 = pw1e6(fmaxf(Xs0 - tm, 0.0f));
        p1 = pw1e6(fmaxf(-tm, 0.0f));
        float fm = (p0 + p1) - 1.0f;
        bool take = (fm * f_lo >= 0.0f);
        if (tm == tau_lo) break;
        if (take) tau_lo = tm;
    }
    pT[i] = p0 / (p0 + p1);
}

// ---------------------------------------------------------------------------
// cumprod over queries per (b,k) column + mask accumulation
// ---------------------------------------------------------------------------
__global__ void k_mask(const float* __restrict__ pT, float* __restrict__ mask) {
    int col = blockIdx.x * blockDim.x + threadIdx.x;
    if (col >= BN*TN) return;
    int b = col >> 10, k = col & (TN-1);
    const float* pr = pT + ((size_t)b*TN + k)*TN;
    float* mcol = mask + (size_t)b*TN*TN + k;
    float c = 1.0f;
#pragma unroll 4
    for (int q = k+1; q < TN; ++q) {
        c = c * pr[q];
        mcol[(size_t)q*TN] += logf(c + 1e-40f);
    }
}

// ---------------------------------------------------------------------------
// Attention: one block per (q, h, b).
// ---------------------------------------------------------------------------
__global__ void k_attn(const float* __restrict__ qkv, const float* __restrict__ mask,
                       float* __restrict__ y) {
    int qi = blockIdx.x, h = blockIdx.y, b = blockIdx.z;
    int tid = threadIdx.x;   // 128
    __shared__ float qs[HDN];
    __shared__ float s[TN];
    __shared__ float red[128];

    const float* base = qkv + (size_t)(b*TN)*3*CN;
    const float* qrow = base + (size_t)qi*3*CN + h*HDN;
    if (tid < HDN) qs[tid] = qrow[tid];
    __syncthreads();

    const float* mrow = mask + ((size_t)(b*TN) + qi)*TN;
    float lmax = -INFINITY;
    for (int k = tid; k <= qi; k += 128) {
        const float* krow = base + (size_t)k*3*CN + CN + h*HDN;
        float dot = 0.0f;
#pragma unroll
        for (int d = 0; d < HDN; d += 4) {
            float4 kv4 = *(const float4*)(krow + d);
            dot += qs[d]*kv4.x + qs[d+1]*kv4.y + qs[d+2]*kv4.z + qs[d+3]*kv4.w;
        }
        float sc = dot*0.125f + mrow[k];
        s[k] = sc;
        lmax = fmaxf(lmax, sc);
    }
    red[tid] = lmax; __syncthreads();
    for (int st = 64; st > 0; st >>= 1) {
        if (tid < st) red[tid] = fmaxf(red[tid], red[tid+st]);
        __syncthreads();
    }
    float m = red[0];
    __syncthreads();

    float lsum = 0.0f;
    for (int k = tid; k <= qi; k += 128) {
        float e = expf(s[k] - m);
        s[k] = e;
        lsum += e;
    }
    red[tid] = lsum; __syncthreads();
    for (int st = 64; st > 0; st >>= 1) {
        if (tid < st) red[tid] += red[tid+st];
        __syncthreads();
    }
    float inv = 1.0f / red[0];
    __syncthreads();

    int d = tid & 63, part = tid >> 6;
    float acc = 0.0f;
    for (int k = part; k <= qi; k += 2)
        acc += s[k] * base[(size_t)k*3*CN + 2*CN + h*HDN + d];
    red[tid] = acc; __syncthreads();
    if (tid < 64) {
        float tot = (red[tid] + red[tid+64]) * inv;
        y[((size_t)(b*TN) + qi)*CN + h*HDN + d] = tot;
    }
}

// ---------------------------------------------------------------------------
// GELU
// ---------------------------------------------------------------------------
__global__ void k_gelu(float* __restrict__ p, int n) {
    int i = blockIdx.x * blockDim.x + threadIdx.x;
    if (i >= n) return;
    float v = p[i];
    float inner = 0.7978845608028654f * (v + 0.044715f*v*v*v);
    p[i] = 0.5f*v*(1.0f + tanhf(inner));
}

// ---------------------------------------------------------------------------
// Host orchestration
// ---------------------------------------------------------------------------
extern "C" void kernel_launch(void* const* d_in, const int* in_sizes, int n_in,
                              void* d_out, int out_size) {
    const float* wte    = (const float*)d_in[0];
    const float* wpe    = (const float*)d_in[1];
    const float* ln1_w  = (const float*)d_in[2];
    const float* ln1_b  = (const float*)d_in[3];
    const float* attn_w = (const float*)d_in[4];
    const float* attn_b = (const float*)d_in[5];
    const float* qint_w = (const float*)d_in[6];
    const float* kint_w = (const float*)d_in[7];
    const float* int_bias = (const float*)d_in[8];
    const float* proj_w = (const float*)d_in[9];
    const float* proj_b = (const float*)d_in[10];
    const float* ln2_w  = (const float*)d_in[11];
    const float* ln2_b  = (const float*)d_in[12];
    const float* fc_w   = (const float*)d_in[13];
    const float* fc_b   = (const float*)d_in[14];
    const float* fc2_w  = (const float*)d_in[15];
    const float* fc2_b  = (const float*)d_in[16];
    const float* lnf_w  = (const float*)d_in[17];
    const float* lnf_b  = (const float*)d_in[18];
    const int*   idx    = (const int*)d_in[19];
    float* out = (float*)d_out;

    float *px, *ph, *pqkv, *py, *pqi, *pki, *pp, *pmask, *pfc;
    cudaGetSymbolAddress((void**)&px,    g_x);
    cudaGetSymbolAddress((void**)&ph,    g_h);
    cudaGetSymbolAddress((void**)&pqkv,  g_qkv);
    cudaGetSymbolAddress((void**)&py,    g_y);
    cudaGetSymbolAddress((void**)&pqi,   g_qi);
    cudaGetSymbolAddress((void**)&pki,   g_ki);
    cudaGetSymbolAddress((void**)&pp,    g_p);
    cudaGetSymbolAddress((void**)&pmask, g_mask);
    cudaGetSymbolAddress((void**)&pfc,   g_fc);

    double am1d = 1.000001 - 1.0;
    float am1f = (float)am1d;
    float halfpow = (float)pow(0.5, am1d);

    k_embed<<<(MN*CN + 255)/256, 256>>>(wte, wpe, idx, px);
    k_zero<<<1024, 256>>>(pmask, BN*TN*TN);

    for (int l = 0; l < LN; ++l) {
        // --- attention sub-block ---
        k_ln<<<MN, 256>>>(px, ln1_w + l*CN, ln1_b + l*CN, ph);
        k_gemm<<<dim3(MN/128, 3*CN/64), 256>>>(ph, attn_w + (size_t)l*3*CN*CN,
                                               attn_b + l*3*CN, nullptr, pqkv, MN, 3*CN, CN);
        k_gemm<<<dim3(MN/128, DIN/64), 256>>>(ph, qint_w + (size_t)l*DIN*CN,
                                              nullptr, nullptr, pqi, MN, DIN, CN);
        k_gemm<<<dim3(MN/128, DIN/64), 256>>>(ph, kint_w + (size_t)l*DIN*CN,
                                              nullptr, nullptr, pki, MN, DIN, CN);
        // rawT[b][k][q] = kint[b,k,:] . qint[b,q,:]
        for (int b = 0; b < BN; ++b)
            k_gemm<<<dim3(TN/128, TN/64), 256>>>(pki + (size_t)b*TN*DIN, pqi + (size_t)b*TN*DIN,
                                                 nullptr, nullptr, pp + (size_t)b*TN*TN,
                                                 TN, TN, DIN);
        k_entmax<<<(BN*TN*TN + 255)/256, 256>>>(pp, int_bias, l, am1f, halfpow);
        k_mask<<<(BN*TN + 127)/128, 128>>>(pp, pmask);
        k_attn<<<dim3(TN, HN, BN), 128>>>(pqkv, pmask, py);
        k_gemm<<<dim3(MN/128, CN/64), 256>>>(py, proj_w + (size_t)l*CN*CN,
                                             proj_b + l*CN, px, px, MN, CN, CN);
        // --- MLP sub-block ---
        k_ln<<<MN, 256>>>(px, ln2_w + l*CN, ln2_b + l*CN, ph);
        k_gemm<<<dim3(MN/128, CFN/64), 256>>>(ph, fc_w + (size_t)l*CFN*CN,
                                              fc_b + l*CFN, nullptr, pfc, MN, CFN, CN);
        k_gelu<<<(MN*CFN + 255)/256, 256>>>(pfc, MN*CFN);
        k_gemm<<<dim3(MN/128, CN/64), 256>>>(pfc, fc2_w + (size_t)l*CN*CFN,
                                             fc2_b + l*CN, px, px, MN, CN, CFN);
    }

    k_ln<<<MN, 256>>>(px, lnf_w, lnf_b, ph);
    k_gemm<<<dim3(MN/128, VN/64), 256>>>(ph, wte, nullptr, nullptr, out, MN, VN, CN);
}

// round 4
// speedup vs baseline: 1.4278x; 1.1386x over previous
#include <cuda_runtime.h>
#include <math.h>
#include <stdint.h>

// ---------------------------------------------------------------------------
// Problem constants
// ---------------------------------------------------------------------------
#define BN 2
#define TN 1024
#define CN 768
#define HN 12
#define HDN 64
#define LN 4
#define DIN 64
#define VN 50304
#define CFN 3072          // 4*C
#define MN (BN*TN)        // 2048 rows

// ---------------------------------------------------------------------------
// Scratch (static device globals; allocation APIs are forbidden)
// ---------------------------------------------------------------------------
__device__ float g_x[MN*CN];
__device__ float g_h[MN*CN];
__device__ float g_qkv[MN*3*CN];
__device__ float g_y[MN*CN];
__device__ float g_qi[MN*DIN];
__device__ float g_ki[MN*DIN];
__device__ float g_p[BN*TN*TN];     // rawT then pT, layout [b][k][q]
__device__ float g_mask[BN*TN*TN];  // accumulated attn_mask, layout [b][q][k]
__device__ float g_fc[MN*CFN];

// ---------------------------------------------------------------------------
// Embedding: x = wte[idx] + wpe[:T]
// ---------------------------------------------------------------------------
__global__ void k_embed(const float* __restrict__ wte, const float* __restrict__ wpe,
                        const int* __restrict__ idx, float* __restrict__ x) {
    int i = blockIdx.x * blockDim.x + threadIdx.x;
    if (i >= MN*CN) return;
    int c = i % CN;
    int bt = i / CN;
    int t = bt % TN;
    x[i] = wte[(size_t)idx[bt]*CN + c] + wpe[t*CN + c];
}

__global__ void k_zero(float* __restrict__ p, int n) {
    int i = blockIdx.x * blockDim.x + threadIdx.x;
    for (; i < n; i += gridDim.x * blockDim.x) p[i] = 0.0f;
}

// ---------------------------------------------------------------------------
// LayerNorm (block per row, C = 768 = 3*256)
// ---------------------------------------------------------------------------
__global__ void k_ln(const float* __restrict__ x, const float* __restrict__ w,
                     const float* __restrict__ b, float* __restrict__ o) {
    int row = blockIdx.x;
    const float* xr = x + (size_t)row*CN;
    float* orow = o + (size_t)row*CN;
    __shared__ float red[256];
    int t = threadIdx.x;
    float lx0 = xr[t], lx1 = xr[t+256], lx2 = xr[t+512];
    red[t] = lx0 + lx1 + lx2;
    __syncthreads();
    for (int st = 128; st > 0; st >>= 1) {
        if (t < st) red[t] += red[t+st];
        __syncthreads();
    }
    float mu = red[0] / (float)CN;
    __syncthreads();
    float d0 = lx0-mu, d1 = lx1-mu, d2 = lx2-mu;
    red[t] = d0*d0 + d1*d1 + d2*d2;
    __syncthreads();
    for (int st = 128; st > 0; st >>= 1) {
        if (t < st) red[t] += red[t+st];
        __syncthreads();
    }
    float var = red[0] / (float)CN;
    float inv = 1.0f / sqrtf(var + 1e-5f);
    orow[t]     = d0*inv*w[t]     + b[t];
    orow[t+256] = d1*inv*w[t+256] + b[t+256];
    orow[t+512] = d2*inv*w[t+512] + b[t+512];
}

// ---------------------------------------------------------------------------
// GELU helper (tanh approximation, matching reference constants)
// ---------------------------------------------------------------------------
__device__ __forceinline__ float gelu1(float v) {
    float inner = 0.7978845608028654f * (v + 0.044715f*v*v*v);
    return 0.5f*v*(1.0f + tanhf(inner));
}

// ---------------------------------------------------------------------------
// 3xTF32 tensor-core GEMM, double-buffered smem pipeline.
// O[m,n] = sum_k A[m,k]*W[n,k] (+bias[n]) (+res[m,n]) (optional gelu)
// A:[M,K] row-major, W:[N,K] row-major. M%128==0, N%64==0, K%16==0.
// Block tile 128x64, BK=16, 8 warps (4Mx2N), warp tile 32x32.
// Grid: x = M/128 (fastest -> M-blocks sharing a W tile run concurrently).
// ---------------------------------------------------------------------------
#define SAS 136   // smem A stride (==8 mod 32 -> conflict-free)
#define SBS 72    // smem B stride (==8 mod 32)
#define SWZ(k, x) ((x) ^ ((((k) >> 2) & 3) << 3))
#define GEMM_SMEM ((2*16*SAS*2 + 2*16*SBS*2) * 4)   // 53248 bytes

__device__ __forceinline__ uint32_t tf32_rna(float v) {
    uint32_t r;
    asm("cvt.rna.tf32.f32 %0, %1;" : "=r"(r) : "f"(v));
    return r;
}

__device__ __forceinline__ void mma_tf32(float* d, const uint32_t* a, const uint32_t* b) {
    asm volatile(
        "mma.sync.aligned.m16n8k8.row.col.f32.tf32.tf32.f32 "
        "{%0,%1,%2,%3}, {%4,%5,%6,%7}, {%8,%9}, {%0,%1,%2,%3};"
        : "+f"(d[0]), "+f"(d[1]), "+f"(d[2]), "+f"(d[3])
        : "r"(a[0]), "r"(a[1]), "r"(a[2]), "r"(a[3]), "r"(b[0]), "r"(b[1]));
}

__global__ __launch_bounds__(256)
void k_gemm(const float* __restrict__ A, const float* __restrict__ W,
            const float* __restrict__ bias, const float* __restrict__ res,
            float* __restrict__ O, int M, int N, int K, int act) {
    extern __shared__ uint32_t dsm[];
    uint32_t* sAh = dsm;                    // [2][16*SAS]
    uint32_t* sAl = sAh + 2*16*SAS;
    uint32_t* sBh = sAl + 2*16*SAS;         // [2][16*SBS]
    uint32_t* sBl = sBh + 2*16*SBS;

    int tid = threadIdx.x;
    int lane = tid & 31, warp = tid >> 5;
    int wm = warp >> 1, wn = warp & 1;           // warp grid 4x2
    int m0 = blockIdx.x * 128, n0 = blockIdx.y * 64;

    int gr = tid >> 2;            // 0..63
    int gc = (tid & 3) * 4;       // 0,4,8,12
    const float* Ap0 = A + (size_t)(m0 + gr)*K + gc;
    const float* Ap1 = A + (size_t)(m0 + gr + 64)*K + gc;
    const float* Bp  = W + (size_t)(n0 + gr)*K + gc;

    // store offsets are k0-invariant: precompute once
    int soA0[4], soA1[4], soB[4];
#pragma unroll
    for (int j = 0; j < 4; j++) {
        int kk = gc + j;
        soA0[j] = kk*SAS + SWZ(kk, gr);
        soA1[j] = kk*SAS + SWZ(kk, gr + 64);
        soB[j]  = kk*SBS + SWZ(kk, gr);
    }

    float acc[2][4][4];
#pragma unroll
    for (int i = 0; i < 2; i++)
#pragma unroll
        for (int j = 0; j < 4; j++)
#pragma unroll
            for (int v = 0; v < 4; v++) acc[i][j][v] = 0.0f;

    int r = lane >> 2, c = lane & 3;

    float4 av0 = *(const float4*)Ap0;
    float4 av1 = *(const float4*)Ap1;
    float4 bv  = *(const float4*)Bp;

    auto cvt_store = [&](int st) {
        uint32_t* pAh = sAh + st*16*SAS;
        uint32_t* pAl = sAl + st*16*SAS;
        uint32_t* pBh = sBh + st*16*SBS;
        uint32_t* pBl = sBl + st*16*SBS;
        float va0[4] = {av0.x, av0.y, av0.z, av0.w};
        float va1[4] = {av1.x, av1.y, av1.z, av1.w};
        float vb_[4] = {bv.x,  bv.y,  bv.z,  bv.w};
#pragma unroll
        for (int j = 0; j < 4; j++) {
            uint32_t h0 = tf32_rna(va0[j]);
            pAh[soA0[j]] = h0;
            pAl[soA0[j]] = tf32_rna(va0[j] - __uint_as_float(h0));
            uint32_t h1 = tf32_rna(va1[j]);
            pAh[soA1[j]] = h1;
            pAl[soA1[j]] = tf32_rna(va1[j] - __uint_as_float(h1));
            uint32_t hb = tf32_rna(vb_[j]);
            pBh[soB[j]] = hb;
            pBl[soB[j]] = tf32_rna(vb_[j] - __uint_as_float(hb));
        }
    };

    auto compute = [&](int st) {
        const uint32_t* pAh = sAh + st*16*SAS;
        const uint32_t* pAl = sAl + st*16*SAS;
        const uint32_t* pBh = sBh + st*16*SBS;
        const uint32_t* pBl = sBl + st*16*SBS;
#pragma unroll
        for (int kk8 = 0; kk8 < 16; kk8 += 8) {
            uint32_t ah[2][4], al[2][4], bh[4][2], bl[4][2];
            int kA0 = kk8 + c, kA1 = kk8 + c + 4;
#pragma unroll
            for (int mf = 0; mf < 2; mf++) {
                int mi = wm*32 + mf*16 + r;
                ah[mf][0] = pAh[kA0*SAS + SWZ(kA0, mi)];
                ah[mf][1] = pAh[kA0*SAS + SWZ(kA0, mi + 8)];
                ah[mf][2] = pAh[kA1*SAS + SWZ(kA1, mi)];
                ah[mf][3] = pAh[kA1*SAS + SWZ(kA1, mi + 8)];
                al[mf][0] = pAl[kA0*SAS + SWZ(kA0, mi)];
                al[mf][1] = pAl[kA0*SAS + SWZ(kA0, mi + 8)];
                al[mf][2] = pAl[kA1*SAS + SWZ(kA1, mi)];
                al[mf][3] = pAl[kA1*SAS + SWZ(kA1, mi + 8)];
            }
#pragma unroll
            for (int nf = 0; nf < 4; nf++) {
                int ni = wn*32 + nf*8 + r;
                bh[nf][0] = pBh[kA0*SBS + SWZ(kA0, ni)];
                bh[nf][1] = pBh[kA1*SBS + SWZ(kA1, ni)];
                bl[nf][0] = pBl[kA0*SBS + SWZ(kA0, ni)];
                bl[nf][1] = pBl[kA1*SBS + SWZ(kA1, ni)];
            }
#pragma unroll
            for (int mf = 0; mf < 2; mf++)
#pragma unroll
                for (int nf = 0; nf < 4; nf++) {
                    mma_tf32(acc[mf][nf], ah[mf], bh[nf]);
                    mma_tf32(acc[mf][nf], ah[mf], bl[nf]);
                    mma_tf32(acc[mf][nf], al[mf], bh[nf]);
                }
        }
    };

    cvt_store(0);
    __syncthreads();

    int nk = K >> 4;
    for (int it = 0; it < nk; ++it) {
        int st = it & 1;
        bool more = (it + 1 < nk);
        if (more) {       // issue next global loads early; latency hidden by compute
            Ap0 += 16; Ap1 += 16; Bp += 16;
            av0 = *(const float4*)Ap0;
            av1 = *(const float4*)Ap1;
            bv  = *(const float4*)Bp;
        }
        compute(st);
        if (more) cvt_store(st ^ 1);
        __syncthreads();
    }

    // epilogue: c0:(r, 2c) c1:(r, 2c+1) c2:(r+8, 2c) c3:(r+8, 2c+1)
#pragma unroll
    for (int mf = 0; mf < 2; mf++) {
        int m = m0 + wm*32 + mf*16 + r;
#pragma unroll
        for (int nf = 0; nf < 4; nf++) {
            int n = n0 + wn*32 + nf*8 + c*2;
            float v0 = acc[mf][nf][0], v1 = acc[mf][nf][1];
            float v2 = acc[mf][nf][2], v3 = acc[mf][nf][3];
            if (bias) {
                float b0 = bias[n], b1 = bias[n+1];
                v0 += b0; v1 += b1; v2 += b0; v3 += b1;
            }
            if (act) {
                v0 = gelu1(v0); v1 = gelu1(v1); v2 = gelu1(v2); v3 = gelu1(v3);
            }
            if (res) {
                v0 += res[(size_t)m*N + n];
                v1 += res[(size_t)m*N + n + 1];
                v2 += res[(size_t)(m+8)*N + n];
                v3 += res[(size_t)(m+8)*N + n + 1];
            }
            O[(size_t)m*N + n]         = v0;
            O[(size_t)m*N + n + 1]     = v1;
            O[(size_t)(m+8)*N + n]     = v2;
            O[(size_t)(m+8)*N + n + 1] = v3;
        }
    }
}

// ---------------------------------------------------------------------------
// entmax (alpha = 1.000001) over the 2-vector [r, 0], bisection, f32-faithful.
// ---------------------------------------------------------------------------
__device__ __forceinline__ float pw1e6(float base) {
    float t = base - 1.0f;                 // exact (base in (0.999, 1.0])
    float u = 1.0e6f * t;
    float e = fmaf(1.0e6f, t, -u);         // exact product residual
    float c = fmaf(u*t, fmaf(t, fmaf(-0.25f, t, 0.33333333333333333f), -0.5f), e);
    return expf(u) * (1.0f + c*(1.0f + 0.5f*c));
}

__global__ void k_entmax(float* __restrict__ pT, const float* __restrict__ int_bias,
                         int l, float am1f, float halfpow) {
    long long i = (long long)blockIdx.x * blockDim.x + threadIdx.x;
    if (i >= (long long)BN*TN*TN) return;
    int q = (int)(i % TN);
    int k = (int)((i / TN) % TN);
    if (q <= k) return;

    float r   = pT[i]*0.125f + int_bias[l];
    float Xs0 = r * am1f;
    float maxv = fmaxf(Xs0, 0.0f);
    float tau_lo = maxv - 1.0f;
    float tau_hi = maxv - halfpow;
    float dm = tau_hi - tau_lo;
    float f_lo = (pw1e6(fmaxf(Xs0 - tau_lo, 0.0f)) + pw1e6(fmaxf(-tau_lo, 0.0f))) - 1.0f;

    float p0 = 0.0f, p1 = 0.0f;
#pragma unroll 1
    for (int it = 0; it < 50; ++it) {
        dm *= 0.5f;
        float tm = tau_lo + dm;
        p0 = pw1e6(fmaxf(Xs0 - tm, 0.0f));
        p1 = pw1e6(fmaxf(-tm, 0.0f));
        float fm = (p0 + p1) - 1.0f;
        bool take = (fm * f_lo >= 0.0f);
        if (tm == tau_lo) break;
        if (take) tau_lo = tm;
    }
    pT[i] = p0 / (p0 + p1);
}

// ---------------------------------------------------------------------------
// mask[b][q][k] += cumsum_{k<q'<=q} log(p[b][k][q'])   (parallel scan per column)
// Equivalent to log(cumprod p + 1e-40) except where cumprod underflows
// (mask < -76 there -> softmax-dead either way; -inf is safe: diagonal is 0).
// One block of 256 per (b,k) column; p is q-contiguous.
// ---------------------------------------------------------------------------
__global__ void k_mask(const float* __restrict__ pT, float* __restrict__ mask) {
    int col = blockIdx.x;
    int b = col >> 10, k = col & (TN-1);
    const float* pr = pT + ((size_t)b*TN + k)*TN;
    float* mcol = mask + (size_t)b*TN*TN + k;
    int tid = threadIdx.x;
    int lane = tid & 31, wid = tid >> 5;
    __shared__ float wsum[8];
    __shared__ float s_carry;
    if (tid == 0) s_carry = 0.0f;
    __syncthreads();

    for (int q0 = 0; q0 < TN; q0 += 256) {
        int q = q0 + tid;
        float v = (q > k) ? logf(pr[q]) : 0.0f;
#pragma unroll
        for (int o = 1; o < 32; o <<= 1) {
            float nv = __shfl_up_sync(0xFFFFFFFFu, v, o);
            if (lane >= o) v += nv;
        }
        if (lane == 31) wsum[wid] = v;
        __syncthreads();
        if (wid == 0) {
            float w = (lane < 8) ? wsum[lane] : 0.0f;
#pragma unroll
            for (int o = 1; o < 8; o <<= 1) {
                float nw = __shfl_up_sync(0xFFFFFFFFu, w, o);
                if (lane >= o) w += nw;
            }
            if (lane < 8) wsum[lane] = w;
        }
        __syncthreads();
        float incl = s_carry + (wid > 0 ? wsum[wid-1] : 0.0f) + v;
        if (q > k) mcol[(size_t)q*TN] += incl;
        __syncthreads();
        if (tid == 255) s_carry = incl;
        __syncthreads();
    }
}

// ---------------------------------------------------------------------------
// Attention: one block per (q, h, b).
// ---------------------------------------------------------------------------
__global__ void k_attn(const float* __restrict__ qkv, const float* __restrict__ mask,
                       float* __restrict__ y) {
    int qi = blockIdx.x, h = blockIdx.y, b = blockIdx.z;
    int tid = threadIdx.x;   // 128
    __shared__ float qs[HDN];
    __shared__ float s[TN];
    __shared__ float red[128];

    const float* base = qkv + (size_t)(b*TN)*3*CN;
    const float* qrow = base + (size_t)qi*3*CN + h*HDN;
    if (tid < HDN) qs[tid] = qrow[tid];
    __syncthreads();

    const float* mrow = mask + ((size_t)(b*TN) + qi)*TN;
    float lmax = -INFINITY;
    for (int k = tid; k <= qi; k += 128) {
        const float* krow = base + (size_t)k*3*CN + CN + h*HDN;
        float dot = 0.0f;
#pragma unroll
        for (int d = 0; d < HDN; d += 4) {
            float4 kv4 = *(const float4*)(krow + d);
            dot += qs[d]*kv4.x + qs[d+1]*kv4.y + qs[d+2]*kv4.z + qs[d+3]*kv4.w;
        }
        float sc = dot*0.125f + mrow[k];
        s[k] = sc;
        lmax = fmaxf(lmax, sc);
    }
    red[tid] = lmax; __syncthreads();
    for (int st = 64; st > 0; st >>= 1) {
        if (tid < st) red[tid] = fmaxf(red[tid], red[tid+st]);
        __syncthreads();
    }
    float m = red[0];
    __syncthreads();

    float lsum = 0.0f;
    for (int k = tid; k <= qi; k += 128) {
        float e = expf(s[k] - m);
        s[k] = e;
        lsum += e;
    }
    red[tid] = lsum; __syncthreads();
    for (int st = 64; st > 0; st >>= 1) {
        if (tid < st) red[tid] += red[tid+st];
        __syncthreads();
    }
    float inv = 1.0f / red[0];
    __syncthreads();

    int d = tid & 63, part = tid >> 6;
    float acc = 0.0f;
    for (int k = part; k <= qi; k += 2)
        acc += s[k] * base[(size_t)k*3*CN + 2*CN + h*HDN + d];
    red[tid] = acc; __syncthreads();
    if (tid < 64) {
        float tot = (red[tid] + red[tid+64]) * inv;
        y[((size_t)(b*TN) + qi)*CN + h*HDN + d] = tot;
    }
}

// ---------------------------------------------------------------------------
// Host orchestration
// ---------------------------------------------------------------------------
extern "C" void kernel_launch(void* const* d_in, const int* in_sizes, int n_in,
                              void* d_out, int out_size) {
    const float* wte    = (const float*)d_in[0];
    const float* wpe    = (const float*)d_in[1];
    const float* ln1_w  = (const float*)d_in[2];
    const float* ln1_b  = (const float*)d_in[3];
    const float* attn_w = (const float*)d_in[4];
    const float* attn_b = (const float*)d_in[5];
    const float* qint_w = (const float*)d_in[6];
    const float* kint_w = (const float*)d_in[7];
    const float* int_bias = (const float*)d_in[8];
    const float* proj_w = (const float*)d_in[9];
    const float* proj_b = (const float*)d_in[10];
    const float* ln2_w  = (const float*)d_in[11];
    const float* ln2_b  = (const float*)d_in[12];
    const float* fc_w   = (const float*)d_in[13];
    const float* fc_b   = (const float*)d_in[14];
    const float* fc2_w  = (const float*)d_in[15];
    const float* fc2_b  = (const float*)d_in[16];
    const float* lnf_w  = (const float*)d_in[17];
    const float* lnf_b  = (const float*)d_in[18];
    const int*   idx    = (const int*)d_in[19];
    float* out = (float*)d_out;

    float *px, *ph, *pqkv, *py, *pqi, *pki, *pp, *pmask, *pfc;
    cudaGetSymbolAddress((void**)&px,    g_x);
    cudaGetSymbolAddress((void**)&ph,    g_h);
    cudaGetSymbolAddress((void**)&pqkv,  g_qkv);
    cudaGetSymbolAddress((void**)&py,    g_y);
    cudaGetSymbolAddress((void**)&pqi,   g_qi);
    cudaGetSymbolAddress((void**)&pki,   g_ki);
    cudaGetSymbolAddress((void**)&pp,    g_p);
    cudaGetSymbolAddress((void**)&pmask, g_mask);
    cudaGetSymbolAddress((void**)&pfc,   g_fc);

    cudaFuncSetAttribute(k_gemm, cudaFuncAttributeMaxDynamicSharedMemorySize, GEMM_SMEM);

    double am1d = 1.000001 - 1.0;
    float am1f = (float)am1d;
    float halfpow = (float)pow(0.5, am1d);

    k_embed<<<(MN*CN + 255)/256, 256>>>(wte, wpe, idx, px);
    k_zero<<<1024, 256>>>(pmask, BN*TN*TN);

    for (int l = 0; l < LN; ++l) {
        // --- attention sub-block ---
        k_ln<<<MN, 256>>>(px, ln1_w + l*CN, ln1_b + l*CN, ph);
        k_gemm<<<dim3(MN/128, 3*CN/64), 256, GEMM_SMEM>>>(ph, attn_w + (size_t)l*3*CN*CN,
                                               attn_b + l*3*CN, nullptr, pqkv, MN, 3*CN, CN, 0);
        k_gemm<<<dim3(MN/128, DIN/64), 256, GEMM_SMEM>>>(ph, qint_w + (size_t)l*DIN*CN,
                                              nullptr, nullptr, pqi, MN, DIN, CN, 0);
        k_gemm<<<dim3(MN/128, DIN/64), 256, GEMM_SMEM>>>(ph, kint_w + (size_t)l*DIN*CN,
                                              nullptr, nullptr, pki, MN, DIN, CN, 0);
        // rawT[b][k][q] = kint[b,k,:] . qint[b,q,:]
        for (int b = 0; b < BN; ++b)
            k_gemm<<<dim3(TN/128, TN/64), 256, GEMM_SMEM>>>(pki + (size_t)b*TN*DIN, pqi + (size_t)b*TN*DIN,
                                                 nullptr, nullptr, pp + (size_t)b*TN*TN,
                                                 TN, TN, DIN, 0);
        k_entmax<<<(BN*TN*TN + 255)/256, 256>>>(pp, int_bias, l, am1f, halfpow);
        k_mask<<<BN*TN, 256>>>(pp, pmask);
        k_attn<<<dim3(TN, HN, BN), 128>>>(pqkv, pmask, py);
        k_gemm<<<dim3(MN/128, CN/64), 256, GEMM_SMEM>>>(py, proj_w + (size_t)l*CN*CN,
                                             proj_b + l*CN, px, px, MN, CN, CN, 0);
        // --- MLP sub-block (GELU fused into fc epilogue) ---
        k_ln<<<MN, 256>>>(px, ln2_w + l*CN, ln2_b + l*CN, ph);
        k_gemm<<<dim3(MN/128, CFN/64), 256, GEMM_SMEM>>>(ph, fc_w + (size_t)l*CFN*CN,
                                              fc_b + l*CFN, nullptr, pfc, MN, CFN, CN, 1);
        k_gemm<<<dim3(MN/128, CN/64), 256, GEMM_SMEM>>>(pfc, fc2_w + (size_t)l*CN*CFN,
                                             fc2_b + l*CN, px, px, MN, CN, CFN, 0);
    }

    k_ln<<<MN, 256>>>(px, lnf_w, lnf_b, ph);
    k_gemm<<<dim3(MN/128, VN/64), 256, GEMM_SMEM>>>(ph, wte, nullptr, nullptr, out, MN, VN, CN, 0);
}

// round 7
// speedup vs baseline: 1.8877x; 1.3220x over previous
#include <cuda_runtime.h>
#include <math.h>
#include <stdint.h>

// ---------------------------------------------------------------------------
// Problem constants
// ---------------------------------------------------------------------------
#define BN 2
#define TN 1024
#define CN 768
#define HN 12
#define HDN 64
#define LN 4
#define DIN 64
#define VN 50304
#define CFN 3072          // 4*C
#define MN (BN*TN)        // 2048 rows

// ---------------------------------------------------------------------------
// Scratch (static device globals; allocation APIs are forbidden)
// ---------------------------------------------------------------------------
__device__ float g_x[MN*CN];
__device__ float g_h[MN*CN];
__device__ float g_qkv[MN*3*CN];
__device__ float g_y[MN*CN];
__device__ float g_qi[MN*DIN];
__device__ float g_ki[MN*DIN];
__device__ float g_p[BN*TN*TN];     // rawT then pT, layout [b][k][q]
__device__ float g_mask[BN*TN*TN];  // accumulated attn_mask, layout [b][q][k]
__device__ float g_fc[MN*CFN];

// ---------------------------------------------------------------------------
// Embedding: x = wte[idx] + wpe[:T]
// ---------------------------------------------------------------------------
__global__ void k_embed(const float* __restrict__ wte, const float* __restrict__ wpe,
                        const int* __restrict__ idx, float* __restrict__ x) {
    int i = blockIdx.x * blockDim.x + threadIdx.x;
    if (i >= MN*CN) return;
    int c = i % CN;
    int bt = i / CN;
    int t = bt % TN;
    x[i] = wte[(size_t)idx[bt]*CN + c] + wpe[t*CN + c];
}

__global__ void k_zero(float* __restrict__ p, int n) {
    int i = blockIdx.x * blockDim.x + threadIdx.x;
    for (; i < n; i += gridDim.x * blockDim.x) p[i] = 0.0f;
}

// ---------------------------------------------------------------------------
// LayerNorm (block per row, C = 768 = 3*256)
// ---------------------------------------------------------------------------
__global__ void k_ln(const float* __restrict__ x, const float* __restrict__ w,
                     const float* __restrict__ b, float* __restrict__ o) {
    int row = blockIdx.x;
    const float* xr = x + (size_t)row*CN;
    float* orow = o + (size_t)row*CN;
    __shared__ float red[256];
    int t = threadIdx.x;
    float lx0 = xr[t], lx1 = xr[t+256], lx2 = xr[t+512];
    red[t] = lx0 + lx1 + lx2;
    __syncthreads();
    for (int st = 128; st > 0; st >>= 1) {
        if (t < st) red[t] += red[t+st];
        __syncthreads();
    }
    float mu = red[0] / (float)CN;
    __syncthreads();
    float d0 = lx0-mu, d1 = lx1-mu, d2 = lx2-mu;
    red[t] = d0*d0 + d1*d1 + d2*d2;
    __syncthreads();
    for (int st = 128; st > 0; st >>= 1) {
        if (t < st) red[t] += red[t+st];
        __syncthreads();
    }
    float var = red[0] / (float)CN;
    float inv = 1.0f / sqrtf(var + 1e-5f);
    orow[t]     = d0*inv*w[t]     + b[t];
    orow[t+256] = d1*inv*w[t+256] + b[t+256];
    orow[t+512] = d2*inv*w[t+512] + b[t+512];
}

// ---------------------------------------------------------------------------
// GELU helper (tanh approximation, matching reference constants)
// ---------------------------------------------------------------------------
__device__ __forceinline__ float gelu1(float v) {
    float inner = 0.7978845608028654f * (v + 0.044715f*v*v*v);
    return 0.5f*v*(1.0f + tanhf(inner));
}

// ---------------------------------------------------------------------------
// 2xBF16 tensor-core GEMM (hi/lo split, hh+hl+lh), double-buffered smem.
// O[m,n] = sum_k A[m,k]*W[n,k] (+bias[n]) (+res[m,n]) (optional gelu)
// A:[M,K] row-major, W:[N,K] row-major. M%128==0, N%64==0, K%32==0.
// Block tile 128x64, BK=16 (8 bf16x2 k-pairs), 8 warps (4Mx2N), warp 32x32.
// Smem layout [kpair][row] (32-bit words = 2 bf16), stride ==8 mod 32,
// swizzle: row ^= 8 when kpair>=4. Store & all fragment loads conflict-free;
// every LDS address = base register + compile-time immediate.
// ---------------------------------------------------------------------------
#define SAS 136                    // A smem stride (words)
#define SBS 72                     // B smem stride
#define ALO (8*SAS)                // A lo-plane offset
#define BOFF (16*SAS)              // B region offset within a stage
#define BLO (8*SBS)                // B lo-plane offset
#define SSTG (16*SAS + 16*SBS)     // words per stage (3328)

__device__ __forceinline__ void mma_bf16(float* d, const uint32_t* a, const uint32_t* b) {
    asm volatile(
        "mma.sync.aligned.m16n8k16.row.col.f32.bf16.bf16.f32 "
        "{%0,%1,%2,%3}, {%4,%5,%6,%7}, {%8,%9}, {%0,%1,%2,%3};"
        : "+f"(d[0]), "+f"(d[1]), "+f"(d[2]), "+f"(d[3])
        : "r"(a[0]), "r"(a[1]), "r"(a[2]), "r"(a[3]), "r"(b[0]), "r"(b[1]));
}

// pack (f0 -> low half, f1 -> high half) hi and residual lo planes
__device__ __forceinline__ void store_pair(uint32_t* su, float f0, float f1, int loOff) {
    uint32_t hi;
    asm("cvt.rn.bf16x2.f32 %0, %1, %2;" : "=r"(hi) : "f"(f1), "f"(f0));
    float h0 = __uint_as_float(hi << 16);
    float h1 = __uint_as_float(hi & 0xFFFF0000u);
    uint32_t lo;
    asm("cvt.rn.bf16x2.f32 %0, %1, %2;" : "=r"(lo) : "f"(f1 - h1), "f"(f0 - h0));
    su[0] = hi;
    su[loOff] = lo;
}

__global__ __launch_bounds__(256)
void k_gemm(const float* __restrict__ A, const float* __restrict__ W,
            const float* __restrict__ bias, const float* __restrict__ res,
            float* __restrict__ O, int M, int N, int K, int act) {
    __shared__ uint32_t sm[2*SSTG];

    int tid = threadIdx.x;
    int lane = tid & 31, warp = tid >> 5;
    int wm = warp >> 1, wn = warp & 1;           // warp grid 4x2
    int m0 = blockIdx.x * 128, n0 = blockIdx.y * 64;

    int gr = tid >> 2;            // 0..63
    int gc = (tid & 3) * 4;       // k offset 0,4,8,12
    const float* Ap0 = A + (size_t)(m0 + gr)*K + gc;
    const float* Ap1 = Ap0 + (size_t)64*K;
    const float* Bp  = W + (size_t)(n0 + gr)*K + gc;

    // store bases: kpairs kp0, kp0+1 ; rows gr (and gr+64 for A)
    int kp0 = (tid & 3) * 2;
    int fst = ((kp0 >> 2) & 1) << 3;
    int RSA = kp0*SAS + (gr ^ fst);
    int RSB = BOFF + kp0*SBS + (gr ^ fst);

    // fragment bases
    int r = lane >> 2, c = lane & 3;
    int RA = c*SAS + wm*32 + r;
    int RB = BOFF + c*SBS + wn*32 + r;

    float acc[2][4][4];
#pragma unroll
    for (int i = 0; i < 2; i++)
#pragma unroll
        for (int j = 0; j < 4; j++)
#pragma unroll
            for (int v = 0; v < 4; v++) acc[i][j][v] = 0.0f;

    float4 av0, av1, bv;
    auto gload = [&]() {
        av0 = *(const float4*)Ap0;
        av1 = *(const float4*)Ap1;
        bv  = *(const float4*)Bp;
        Ap0 += 16; Ap1 += 16; Bp += 16;
    };

    auto cstore = [&](uint32_t* s) {
        store_pair(s + RSA,            av0.x, av0.y, ALO);
        store_pair(s + RSA + SAS,      av0.z, av0.w, ALO);
        store_pair(s + RSA + 64,       av1.x, av1.y, ALO);
        store_pair(s + RSA + SAS + 64, av1.z, av1.w, ALO);
        store_pair(s + RSB,            bv.x,  bv.y,  BLO);
        store_pair(s + RSB + SBS,      bv.z,  bv.w,  BLO);
    };

    auto comp = [&](const uint32_t* s) {
        uint32_t ah[2][4], al[2][4], bh[4][2], bl[4][2];
#pragma unroll
        for (int mf = 0; mf < 2; mf++) {
            int ba = RA + mf*16;
            ah[mf][0] = s[ba];
            ah[mf][1] = s[ba + 8];
            ah[mf][2] = s[ba + 4*SAS + 8];
            ah[mf][3] = s[ba + 4*SAS];
            al[mf][0] = s[ba + ALO];
            al[mf][1] = s[ba + ALO + 8];
            al[mf][2] = s[ba + ALO + 4*SAS + 8];
            al[mf][3] = s[ba + ALO + 4*SAS];
        }
#pragma unroll
        for (int nf = 0; nf < 4; nf++) {
            int bb = RB + nf*8;
            int o2 = 4*SBS + ((nf & 1) ? -8 : 8);
            bh[nf][0] = s[bb];
            bh[nf][1] = s[bb + o2];
            bl[nf][0] = s[bb + BLO];
            bl[nf][1] = s[bb + BLO + o2];
        }
#pragma unroll
        for (int mf = 0; mf < 2; mf++)
#pragma unroll
            for (int nf = 0; nf < 4; nf++) {
                mma_bf16(acc[mf][nf], ah[mf], bh[nf]);
                mma_bf16(acc[mf][nf], ah[mf], bl[nf]);
                mma_bf16(acc[mf][nf], al[mf], bh[nf]);
            }
    };

    int nk = K >> 4;   // BK=16; all K here are multiples of 32 -> nk even
    gload();
    cstore(sm);
    __syncthreads();
    for (int i2 = 0; i2 < nk; i2 += 2) {
        gload();                       // tile i2+1
        comp(sm);                      // stage 0 (tile i2)
        cstore(sm + SSTG);
        __syncthreads();
        bool more = (i2 + 2 < nk);
        if (more) gload();             // tile i2+2
        comp(sm + SSTG);               // stage 1 (tile i2+1)
        if (more) cstore(sm);
        __syncthreads();
    }

    // epilogue: c0:(r, 2c) c1:(r, 2c+1) c2:(r+8, 2c) c3:(r+8, 2c+1)
#pragma unroll
    for (int mf = 0; mf < 2; mf++) {
        int m = m0 + wm*32 + mf*16 + r;
#pragma unroll
        for (int nf = 0; nf < 4; nf++) {
            int n = n0 + wn*32 + nf*8 + c*2;
            float v0 = acc[mf][nf][0], v1 = acc[mf][nf][1];
            float v2 = acc[mf][nf][2], v3 = acc[mf][nf][3];
            if (bias) {
                float b0 = bias[n], b1 = bias[n+1];
                v0 += b0; v1 += b1; v2 += b0; v3 += b1;
            }
            if (act) {
                v0 = gelu1(v0); v1 = gelu1(v1); v2 = gelu1(v2); v3 = gelu1(v3);
            }
            if (res) {
                v0 += res[(size_t)m*N + n];
                v1 += res[(size_t)m*N + n + 1];
                v2 += res[(size_t)(m+8)*N + n];
                v3 += res[(size_t)(m+8)*N + n + 1];
            }
            O[(size_t)m*N + n]         = v0;
            O[(size_t)m*N + n + 1]     = v1;
            O[(size_t)(m+8)*N + n]     = v2;
            O[(size_t)(m+8)*N + n + 1] = v3;
        }
    }
}

// ---------------------------------------------------------------------------
// entmax (alpha = 1.000001) over the 2-vector [r, 0], bisection, f32-faithful.
// ---------------------------------------------------------------------------
__device__ __forceinline__ float pw1e6(float base) {
    float t = base - 1.0f;                 // exact (base in (0.999, 1.0])
    float u = 1.0e6f * t;
    float e = fmaf(1.0e6f, t, -u);         // exact product residual
    float c = fmaf(u*t, fmaf(t, fmaf(-0.25f, t, 0.33333333333333333f), -0.5f), e);
    return expf(u) * (1.0f + c*(1.0f + 0.5f*c));
}

__global__ void k_entmax(float* __restrict__ pT, const float* __restrict__ int_bias,
                         int l, float am1f, float halfpow) {
    long long i = (long long)blockIdx.x * blockDim.x + threadIdx.x;
    if (i >= (long long)BN*TN*TN) return;
    int q = (int)(i % TN);
    int k = (int)((i / TN) % TN);
    if (q <= k) return;

    float r   = pT[i]*0.125f + int_bias[l];
    float Xs0 = r * am1f;
    float maxv = fmaxf(Xs0, 0.0f);
    float tau_lo = maxv - 1.0f;
    float tau_hi = maxv - halfpow;
    float dm = tau_hi - tau_lo;
    float f_lo = (pw1e6(fmaxf(Xs0 - tau_lo, 0.0f)) + pw1e6(fmaxf(-tau_lo, 0.0f))) - 1.0f;

    float p0 = 0.0f, p1 = 0.0f;
#pragma unroll 1
    for (int it = 0; it < 50; ++it) {
        dm *= 0.5f;
        float tm = tau_lo + dm;
        p0 = pw1e6(fmaxf(Xs0 - tm, 0.0f));
        p1 = pw1e6(fmaxf(-tm, 0.0f));
        float fm = (p0 + p1) - 1.0f;
        bool take = (fm * f_lo >= 0.0f);
        if (tm == tau_lo) break;
        if (take) tau_lo = tm;
    }
    pT[i] = p0 / (p0 + p1);
}

// ---------------------------------------------------------------------------
// mask[b][q][k] += cumsum_{k<q'<=q} log(p[b][k][q'])   (parallel scan per column)
// ---------------------------------------------------------------------------
__global__ void k_mask(const float* __restrict__ pT, float* __restrict__ mask) {
    int col = blockIdx.x;
    int b = col >> 10, k = col & (TN-1);
    const float* pr = pT + ((size_t)b*TN + k)*TN;
    float* mcol = mask + (size_t)b*TN*TN + k;
    int tid = threadIdx.x;
    int lane = tid & 31, wid = tid >> 5;
    __shared__ float wsum[8];
    __shared__ float s_carry;
    if (tid == 0) s_carry = 0.0f;
    __syncthreads();

    for (int q0 = 0; q0 < TN; q0 += 256) {
        int q = q0 + tid;
        float v = (q > k) ? logf(pr[q]) : 0.0f;
#pragma unroll
        for (int o = 1; o < 32; o <<= 1) {
            float nv = __shfl_up_sync(0xFFFFFFFFu, v, o);
            if (lane >= o) v += nv;
        }
        if (lane == 31) wsum[wid] = v;
        __syncthreads();
        if (wid == 0) {
            float w = (lane < 8) ? wsum[lane] : 0.0f;
#pragma unroll
            for (int o = 1; o < 8; o <<= 1) {
                float nw = __shfl_up_sync(0xFFFFFFFFu, w, o);
                if (lane >= o) w += nw;
            }
            if (lane < 8) wsum[lane] = w;
        }
        __syncthreads();
        float incl = s_carry + (wid > 0 ? wsum[wid-1] : 0.0f) + v;
        if (q > k) mcol[(size_t)q*TN] += incl;
        __syncthreads();
        if (tid == 255) s_carry = incl;
        __syncthreads();
    }
}

// ---------------------------------------------------------------------------
// Attention: one block per (q, h, b).
// ---------------------------------------------------------------------------
__global__ void k_attn(const float* __restrict__ qkv, const float* __restrict__ mask,
                       float* __restrict__ y) {
    int qi = blockIdx.x, h = blockIdx.y, b = blockIdx.z;
    int tid = threadIdx.x;   // 128
    __shared__ float qs[HDN];
    __shared__ float s[TN];
    __shared__ float red[128];

    const float* base = qkv + (size_t)(b*TN)*3*CN;
    const float* qrow = base + (size_t)qi*3*CN + h*HDN;
    if (tid < HDN) qs[tid] = qrow[tid];
    __syncthreads();

    const float* mrow = mask + ((size_t)(b*TN) + qi)*TN;
    float lmax = -INFINITY;
    for (int k = tid; k <= qi; k += 128) {
        const float* krow = base + (size_t)k*3*CN + CN + h*HDN;
        float dot = 0.0f;
#pragma unroll
        for (int d = 0; d < HDN; d += 4) {
            float4 kv4 = *(const float4*)(krow + d);
            dot += qs[d]*kv4.x + qs[d+1]*kv4.y + qs[d+2]*kv4.z + qs[d+3]*kv4.w;
        }
        float sc = dot*0.125f + mrow[k];
        s[k] = sc;
        lmax = fmaxf(lmax, sc);
    }
    red[tid] = lmax; __syncthreads();
    for (int st = 64; st > 0; st >>= 1) {
        if (tid < st) red[tid] = fmaxf(red[tid], red[tid+st]);
        __syncthreads();
    }
    float m = red[0];
    __syncthreads();

    float lsum = 0.0f;
    for (int k = tid; k <= qi; k += 128) {
        float e = expf(s[k] - m);
        s[k] = e;
        lsum += e;
    }
    red[tid] = lsum; __syncthreads();
    for (int st = 64; st > 0; st >>= 1) {
        if (tid < st) red[tid] += red[tid+st];
        __syncthreads();
    }
    float inv = 1.0f / red[0];
    __syncthreads();

    int d = tid & 63, part = tid >> 6;
    float acc = 0.0f;
    for (int k = part; k <= qi; k += 2)
        acc += s[k] * base[(size_t)k*3*CN + 2*CN + h*HDN + d];
    red[tid] = acc; __syncthreads();
    if (tid < 64) {
        float tot = (red[tid] + red[tid+64]) * inv;
        y[((size_t)(b*TN) + qi)*CN + h*HDN + d] = tot;
    }
}

// ---------------------------------------------------------------------------
// Host orchestration
// ---------------------------------------------------------------------------
extern "C" void kernel_launch(void* const* d_in, const int* in_sizes, int n_in,
                              void* d_out, int out_size) {
    const float* wte    = (const float*)d_in[0];
    const float* wpe    = (const float*)d_in[1];
    const float* ln1_w  = (const float*)d_in[2];
    const float* ln1_b  = (const float*)d_in[3];
    const float* attn_w = (const float*)d_in[4];
    const float* attn_b = (const float*)d_in[5];
    const float* qint_w = (const float*)d_in[6];
    const float* kint_w = (const float*)d_in[7];
    const float* int_bias = (const float*)d_in[8];
    const float* proj_w = (const float*)d_in[9];
    const float* proj_b = (const float*)d_in[10];
    const float* ln2_w  = (const float*)d_in[11];
    const float* ln2_b  = (const float*)d_in[12];
    const float* fc_w   = (const float*)d_in[13];
    const float* fc_b   = (const float*)d_in[14];
    const float* fc2_w  = (const float*)d_in[15];
    const float* fc2_b  = (const float*)d_in[16];
    const float* lnf_w  = (const float*)d_in[17];
    const float* lnf_b  = (const float*)d_in[18];
    const int*   idx    = (const int*)d_in[19];
    float* out = (float*)d_out;

    float *px, *ph, *pqkv, *py, *pqi, *pki, *pp, *pmask, *pfc;
    cudaGetSymbolAddress((void**)&px,    g_x);
    cudaGetSymbolAddress((void**)&ph,    g_h);
    cudaGetSymbolAddress((void**)&pqkv,  g_qkv);
    cudaGetSymbolAddress((void**)&py,    g_y);
    cudaGetSymbolAddress((void**)&pqi,   g_qi);
    cudaGetSymbolAddress((void**)&pki,   g_ki);
    cudaGetSymbolAddress((void**)&pp,    g_p);
    cudaGetSymbolAddress((void**)&pmask, g_mask);
    cudaGetSymbolAddress((void**)&pfc,   g_fc);

    double am1d = 1.000001 - 1.0;
    float am1f = (float)am1d;
    float halfpow = (float)pow(0.5, am1d);

    k_embed<<<(MN*CN + 255)/256, 256>>>(wte, wpe, idx, px);
    k_zero<<<1024, 256>>>(pmask, BN*TN*TN);

    for (int l = 0; l < LN; ++l) {
        // --- attention sub-block ---
        k_ln<<<MN, 256>>>(px, ln1_w + l*CN, ln1_b + l*CN, ph);
        k_gemm<<<dim3(MN/128, 3*CN/64), 256>>>(ph, attn_w + (size_t)l*3*CN*CN,
                                               attn_b + l*3*CN, nullptr, pqkv, MN, 3*CN, CN, 0);
        k_gemm<<<dim3(MN/128, DIN/64), 256>>>(ph, qint_w + (size_t)l*DIN*CN,
                                              nullptr, nullptr, pqi, MN, DIN, CN, 0);
        k_gemm<<<dim3(MN/128, DIN/64), 256>>>(ph, kint_w + (size_t)l*DIN*CN,
                                              nullptr, nullptr, pki, MN, DIN, CN, 0);
        // rawT[b][k][q] = kint[b,k,:] . qint[b,q,:]
        for (int b = 0; b < BN; ++b)
            k_gemm<<<dim3(TN/128, TN/64), 256>>>(pki + (size_t)b*TN*DIN, pqi + (size_t)b*TN*DIN,
                                                 nullptr, nullptr, pp + (size_t)b*TN*TN,
                                                 TN, TN, DIN, 0);
        k_entmax<<<(BN*TN*TN + 255)/256, 256>>>(pp, int_bias, l, am1f, halfpow);
        k_mask<<<BN*TN, 256>>>(pp, pmask);
        k_attn<<<dim3(TN, HN, BN), 128>>>(pqkv, pmask, py);
        k_gemm<<<dim3(MN/128, CN/64), 256>>>(py, proj_w + (size_t)l*CN*CN,
                                             proj_b + l*CN, px, px, MN, CN, CN, 0);
        // --- MLP sub-block (GELU fused into fc epilogue) ---
        k_ln<<<MN, 256>>>(px, ln2_w + l*CN, ln2_b + l*CN, ph);
        k_gemm<<<dim3(MN/128, CFN/64), 256>>>(ph, fc_w + (size_t)l*CFN*CN,
                                              fc_b + l*CFN, nullptr, pfc, MN, CFN, CN, 1);
        k_gemm<<<dim3(MN/128, CN/64), 256>>>(pfc, fc2_w + (size_t)l*CN*CFN,
                                             fc2_b + l*CN, px, px, MN, CN, CFN, 0);
    }

    k_ln<<<MN, 256>>>(px, lnf_w, lnf_b, ph);
    k_gemm<<<dim3(MN/128, VN/64), 256>>>(ph, wte, nullptr, nullptr, out, MN, VN, CN, 0);
}

// round 8
// speedup vs baseline: 2.1068x; 1.1161x over previous
#include <cuda_runtime.h>
#include <math.h>
#include <stdint.h>

// ---------------------------------------------------------------------------
// Problem constants
// ---------------------------------------------------------------------------
#define BN 2
#define TN 1024
#define CN 768
#define HN 12
#define HDN 64
#define LN 4
#define DIN 64
#define VN 50304
#define CFN 3072          // 4*C
#define MN (BN*TN)        // 2048 rows

// ---------------------------------------------------------------------------
// Scratch (static device globals; allocation APIs are forbidden)
// ---------------------------------------------------------------------------
__device__ float g_x[MN*CN];
__device__ float g_h[MN*CN];
__device__ float g_qkv[MN*3*CN];
__device__ float g_y[MN*CN];
__device__ float g_qi[MN*DIN];
__device__ float g_ki[MN*DIN];
__device__ float g_p[BN*TN*TN];     // rawT then log-p, layout [b][k][q]
__device__ float g_mask[BN*TN*TN];  // accumulated attn_mask, layout [b][q][k]
__device__ float g_fc[MN*CFN];

// ---------------------------------------------------------------------------
// Embedding: x = wte[idx] + wpe[:T]
// ---------------------------------------------------------------------------
__global__ void k_embed(const float* __restrict__ wte, const float* __restrict__ wpe,
                        const int* __restrict__ idx, float* __restrict__ x) {
    int i = blockIdx.x * blockDim.x + threadIdx.x;
    if (i >= MN*CN) return;
    int c = i % CN;
    int bt = i / CN;
    int t = bt % TN;
    x[i] = wte[(size_t)idx[bt]*CN + c] + wpe[t*CN + c];
}

__global__ void k_zero(float* __restrict__ p, int n) {
    int i = blockIdx.x * blockDim.x + threadIdx.x;
    for (; i < n; i += gridDim.x * blockDim.x) p[i] = 0.0f;
}

// ---------------------------------------------------------------------------
// LayerNorm (block per row, C = 768 = 3*256)
// ---------------------------------------------------------------------------
__global__ void k_ln(const float* __restrict__ x, const float* __restrict__ w,
                     const float* __restrict__ b, float* __restrict__ o) {
    int row = blockIdx.x;
    const float* xr = x + (size_t)row*CN;
    float* orow = o + (size_t)row*CN;
    __shared__ float red[256];
    int t = threadIdx.x;
    float lx0 = xr[t], lx1 = xr[t+256], lx2 = xr[t+512];
    red[t] = lx0 + lx1 + lx2;
    __syncthreads();
    for (int st = 128; st > 0; st >>= 1) {
        if (t < st) red[t] += red[t+st];
        __syncthreads();
    }
    float mu = red[0] / (float)CN;
    __syncthreads();
    float d0 = lx0-mu, d1 = lx1-mu, d2 = lx2-mu;
    red[t] = d0*d0 + d1*d1 + d2*d2;
    __syncthreads();
    for (int st = 128; st > 0; st >>= 1) {
        if (t < st) red[t] += red[t+st];
        __syncthreads();
    }
    float var = red[0] / (float)CN;
    float inv = 1.0f / sqrtf(var + 1e-5f);
    orow[t]     = d0*inv*w[t]     + b[t];
    orow[t+256] = d1*inv*w[t+256] + b[t+256];
    orow[t+512] = d2*inv*w[t+512] + b[t+512];
}

// ---------------------------------------------------------------------------
// GELU helper (tanh approximation, matching reference constants)
// ---------------------------------------------------------------------------
__device__ __forceinline__ float gelu1(float v) {
    float inner = 0.7978845608028654f * (v + 0.044715f*v*v*v);
    return 0.5f*v*(1.0f + tanhf(inner));
}

// ---------------------------------------------------------------------------
// 2xBF16 tensor-core GEMM (hi/lo split, hh+hl+lh), double-buffered smem,
// ldmatrix fragment loads.
// O[m,n] = sum_k A[m,k]*W[n,k] (+bias[n]) (+res[m,n]) (optional gelu)
// A:[M,K] row-major, W:[N,K] row-major. M%128==0, N%64==0, K%32==0.
// Block tile 128x64, BK=16, 8 warps (4Mx2N), warp tile 32x32.
// Smem per stage: Ahi[128x16 bf16] Alo Bhi[64x16] Blo as 32B rows with
// SW128 swizzle (x ^ ((x>>3)&0x70)): STS.64 store phases and LDSM 8x16B
// tile fetches both bank-conflict-free (verified by bank arithmetic).
// ---------------------------------------------------------------------------
#define SWZB(x) ((x) ^ (((x) >> 3) & 0x70))
#define STGB 12288     // bytes per stage: Ahi 4096 | Alo 4096 | Bhi 2048 | Blo 2048

__device__ __forceinline__ void ldsm4(uint32_t* r, uint32_t addr) {
    asm volatile("ldmatrix.sync.aligned.m8n8.x4.shared.b16 {%0,%1,%2,%3}, [%4];"
        : "=r"(r[0]), "=r"(r[1]), "=r"(r[2]), "=r"(r[3]) : "r"(addr));
}

__device__ __forceinline__ void mma_bf16(float* d, const uint32_t* a, const uint32_t* b) {
    asm volatile(
        "mma.sync.aligned.m16n8k16.row.col.f32.bf16.bf16.f32 "
        "{%0,%1,%2,%3}, {%4,%5,%6,%7}, {%8,%9}, {%0,%1,%2,%3};"
        : "+f"(d[0]), "+f"(d[1]), "+f"(d[2]), "+f"(d[3])
        : "r"(a[0]), "r"(a[1]), "r"(a[2]), "r"(a[3]), "r"(b[0]), "r"(b[1]));
}

// split 4 floats into hi/lo bf16x2 pairs and store 8B to each plane
__device__ __forceinline__ void split_store(char* hiP, char* loP, float4 v) {
    uint32_t h0, h1, l0, l1;
    asm("cvt.rn.bf16x2.f32 %0, %1, %2;" : "=r"(h0) : "f"(v.y), "f"(v.x));
    asm("cvt.rn.bf16x2.f32 %0, %1, %2;" : "=r"(h1) : "f"(v.w), "f"(v.z));
    float e0 = v.x - __uint_as_float(h0 << 16);
    float e1 = v.y - __uint_as_float(h0 & 0xFFFF0000u);
    float e2 = v.z - __uint_as_float(h1 << 16);
    float e3 = v.w - __uint_as_float(h1 & 0xFFFF0000u);
    asm("cvt.rn.bf16x2.f32 %0, %1, %2;" : "=r"(l0) : "f"(e1), "f"(e0));
    asm("cvt.rn.bf16x2.f32 %0, %1, %2;" : "=r"(l1) : "f"(e3), "f"(e2));
    *(uint2*)hiP = make_uint2(h0, h1);
    *(uint2*)loP = make_uint2(l0, l1);
}

__global__ __launch_bounds__(256, 2)
void k_gemm(const float* __restrict__ A, const float* __restrict__ W,
            const float* __restrict__ bias, const float* __restrict__ res,
            float* __restrict__ O, int M, int N, int K, int act) {
    __shared__ __align__(1024) char sm[2*STGB];
    uint32_t sb32 = (uint32_t)__cvta_generic_to_shared(sm);

    int tid = threadIdx.x;
    int lane = tid & 31, warp = tid >> 5;
    int wm = warp >> 1, wn = warp & 1;           // warp grid 4x2
    int m0 = blockIdx.x * 128, n0 = blockIdx.y * 64;

    int gr = tid >> 2;            // row 0..63
    int j8 = (tid & 3) * 8;       // byte offset within 32B row
    const float* Ap0 = A + (size_t)(m0 + gr)*K + (tid & 3)*4;
    const float* Ap1 = Ap0 + (size_t)64*K;
    const float* Bp  = W + (size_t)(n0 + gr)*K + (tid & 3)*4;

    // store offsets (within plane)
    int offA0 = SWZB(gr*32 + j8);
    int offA1 = SWZB((gr+64)*32 + j8);
    // offB == offA0 (same formula, B region base differs)

    // ldmatrix addresses (stage-0; add stage offset in loop)
    int mrow = wm*32 + (lane & 15);
    int aseg = (lane >> 4) & 1;
    uint32_t adr_a0 = sb32 + SWZB(mrow*32 + aseg*16);
    uint32_t adr_a1 = sb32 + SWZB((mrow+16)*32 + aseg*16);
    int nrow = wn*32 + (lane & 7) + ((lane >> 4) << 3);
    int bseg = (lane >> 3) & 1;
    uint32_t adr_b0 = sb32 + 8192 + SWZB(nrow*32 + bseg*16);
    uint32_t adr_b1 = sb32 + 8192 + SWZB((nrow+16)*32 + bseg*16);

    float acc[2][4][4];
#pragma unroll
    for (int i = 0; i < 2; i++)
#pragma unroll
        for (int j = 0; j < 4; j++)
#pragma unroll
            for (int v = 0; v < 4; v++) acc[i][j][v] = 0.0f;

    int r = lane >> 2, c = lane & 3;

    float4 av0, av1, bv;
    auto gload = [&]() {
        av0 = *(const float4*)Ap0;
        av1 = *(const float4*)Ap1;
        bv  = *(const float4*)Bp;
        Ap0 += 16; Ap1 += 16; Bp += 16;
    };

    auto cstore = [&](char* st) {
        split_store(st + offA0,        st + 4096 + offA0, av0);
        split_store(st + offA1,        st + 4096 + offA1, av1);
        split_store(st + 8192 + offA0, st + 10240 + offA0, bv);
    };

    auto comp = [&](uint32_t so) {
        uint32_t ah[2][4], al[2][4], bh[4][2], bl[4][2], t[4];
        ldsm4(ah[0], adr_a0 + so);
        ldsm4(ah[1], adr_a1 + so);
        ldsm4(al[0], adr_a0 + so + 4096);
        ldsm4(al[1], adr_a1 + so + 4096);
        ldsm4(t, adr_b0 + so);
        bh[0][0]=t[0]; bh[0][1]=t[1]; bh[1][0]=t[2]; bh[1][1]=t[3];
        ldsm4(t, adr_b1 + so);
        bh[2][0]=t[0]; bh[2][1]=t[1]; bh[3][0]=t[2]; bh[3][1]=t[3];
        ldsm4(t, adr_b0 + so + 2048);
        bl[0][0]=t[0]; bl[0][1]=t[1]; bl[1][0]=t[2]; bl[1][1]=t[3];
        ldsm4(t, adr_b1 + so + 2048);
        bl[2][0]=t[0]; bl[2][1]=t[1]; bl[3][0]=t[2]; bl[3][1]=t[3];
#pragma unroll
        for (int mf = 0; mf < 2; mf++)
#pragma unroll
            for (int nf = 0; nf < 4; nf++) {
                mma_bf16(acc[mf][nf], ah[mf], bh[nf]);
                mma_bf16(acc[mf][nf], ah[mf], bl[nf]);
                mma_bf16(acc[mf][nf], al[mf], bh[nf]);
            }
    };

    int nk = K >> 4;   // all K multiples of 32 -> nk even
    gload();
    cstore(sm);
    __syncthreads();
    for (int i2 = 0; i2 < nk; i2 += 2) {
        gload();                       // tile i2+1
        comp(0);                       // stage 0 (tile i2)
        cstore(sm + STGB);
        __syncthreads();
        bool more = (i2 + 2 < nk);
        if (more) gload();             // tile i2+2
        comp(STGB);                    // stage 1 (tile i2+1)
        if (more) cstore(sm);
        __syncthreads();
    }

    // epilogue: c0:(r, 2c) c1:(r, 2c+1) c2:(r+8, 2c) c3:(r+8, 2c+1)
#pragma unroll
    for (int mf = 0; mf < 2; mf++) {
        int m = m0 + wm*32 + mf*16 + r;
#pragma unroll
        for (int nf = 0; nf < 4; nf++) {
            int n = n0 + wn*32 + nf*8 + c*2;
            float v0 = acc[mf][nf][0], v1 = acc[mf][nf][1];
            float v2 = acc[mf][nf][2], v3 = acc[mf][nf][3];
            if (bias) {
                float b0 = bias[n], b1 = bias[n+1];
                v0 += b0; v1 += b1; v2 += b0; v3 += b1;
            }
            if (act) {
                v0 = gelu1(v0); v1 = gelu1(v1); v2 = gelu1(v2); v3 = gelu1(v3);
            }
            if (res) {
                v0 += res[(size_t)m*N + n];
                v1 += res[(size_t)m*N + n + 1];
                v2 += res[(size_t)(m+8)*N + n];
                v3 += res[(size_t)(m+8)*N + n + 1];
            }
            O[(size_t)m*N + n]         = v0;
            O[(size_t)m*N + n + 1]     = v1;
            O[(size_t)(m+8)*N + n]     = v2;
            O[(size_t)(m+8)*N + n + 1] = v3;
        }
    }
}

// ---------------------------------------------------------------------------
// entmax (alpha = 1.000001), closed form.
// The reference's f32 bisection freezes at tau within 3e-5 of -1+max; the
// normalized output p0/(p0+p1) = ((Xs0-tau)/(-tau))^1e6 is tau-invariant to
// ~4e-7 over that range, giving p = sigmoid(1e6*log1p(Xs0)) exactly (to ulp).
// Stores log(p) directly (k_mask sums logs).
// ---------------------------------------------------------------------------
__global__ void k_entmax(float* __restrict__ pT, const float* __restrict__ int_bias,
                         int l, float am1f) {
    long long i = (long long)blockIdx.x * blockDim.x + threadIdx.x;
    if (i >= (long long)BN*TN*TN) return;
    int q = (int)(i % TN);
    int k = (int)((i / TN) % TN);
    if (q <= k) return;

    float r = pT[i]*0.125f + int_bias[l];
    float t = r * am1f;                         // Xs0, |t| <= ~4e-5
    // z = 1e6 * log1p(t)  (series: t - t^2/2 + t^3/3)
    float z = 1.0e6f * t * fmaf(t, fmaf(t, 0.33333334f, -0.5f), 1.0f);
    // log p = -log1p(exp(-z)), numerically stable on both sides
    float lp;
    if (z >= 0.0f) lp = -log1pf(expf(-z));
    else           lp = z - log1pf(expf(z));
    pT[i] = lp;
}

// ---------------------------------------------------------------------------
// mask[b][q][k] += cumsum_{k<q'<=q} logp[b][k][q']   (parallel scan per column)
// ---------------------------------------------------------------------------
__global__ void k_mask(const float* __restrict__ pT, float* __restrict__ mask) {
    int col = blockIdx.x;
    int b = col >> 10, k = col & (TN-1);
    const float* pr = pT + ((size_t)b*TN + k)*TN;
    float* mcol = mask + (size_t)b*TN*TN + k;
    int tid = threadIdx.x;
    int lane = tid & 31, wid = tid >> 5;
    __shared__ float wsum[8];
    __shared__ float s_carry;
    if (tid == 0) s_carry = 0.0f;
    __syncthreads();

    for (int q0 = 0; q0 < TN; q0 += 256) {
        int q = q0 + tid;
        float v = (q > k) ? pr[q] : 0.0f;
#pragma unroll
        for (int o = 1; o < 32; o <<= 1) {
            float nv = __shfl_up_sync(0xFFFFFFFFu, v, o);
            if (lane >= o) v += nv;
        }
        if (lane == 31) wsum[wid] = v;
        __syncthreads();
        if (wid == 0) {
            float w = (lane < 8) ? wsum[lane] : 0.0f;
#pragma unroll
            for (int o = 1; o < 8; o <<= 1) {
                float nw = __shfl_up_sync(0xFFFFFFFFu, w, o);
                if (lane >= o) w += nw;
            }
            if (lane < 8) wsum[lane] = w;
        }
        __syncthreads();
        float incl = s_carry + (wid > 0 ? wsum[wid-1] : 0.0f) + v;
        if (q > k) mcol[(size_t)q*TN] += incl;
        __syncthreads();
        if (tid == 255) s_carry = incl;
        __syncthreads();
    }
}

// ---------------------------------------------------------------------------
// Attention: one block per (q, h, b).
// ---------------------------------------------------------------------------
__global__ void k_attn(const float* __restrict__ qkv, const float* __restrict__ mask,
                       float* __restrict__ y) {
    int qi = blockIdx.x, h = blockIdx.y, b = blockIdx.z;
    int tid = threadIdx.x;   // 128
    __shared__ float qs[HDN];
    __shared__ float s[TN];
    __shared__ float red[128];

    const float* base = qkv + (size_t)(b*TN)*3*CN;
    const float* qrow = base + (size_t)qi*3*CN + h*HDN;
    if (tid < HDN) qs[tid] = qrow[tid];
    __syncthreads();

    const float* mrow = mask + ((size_t)(b*TN) + qi)*TN;
    float lmax = -INFINITY;
    for (int k = tid; k <= qi; k += 128) {
        const float* krow = base + (size_t)k*3*CN + CN + h*HDN;
        float dot = 0.0f;
#pragma unroll
        for (int d = 0; d < HDN; d += 4) {
            float4 kv4 = *(const float4*)(krow + d);
            dot += qs[d]*kv4.x + qs[d+1]*kv4.y + qs[d+2]*kv4.z + qs[d+3]*kv4.w;
        }
        float sc = dot*0.125f + mrow[k];
        s[k] = sc;
        lmax = fmaxf(lmax, sc);
    }
    red[tid] = lmax; __syncthreads();
    for (int st = 64; st > 0; st >>= 1) {
        if (tid < st) red[tid] = fmaxf(red[tid], red[tid+st]);
        __syncthreads();
    }
    float m = red[0];
    __syncthreads();

    float lsum = 0.0f;
    for (int k = tid; k <= qi; k += 128) {
        float e = expf(s[k] - m);
        s[k] = e;
        lsum += e;
    }
    red[tid] = lsum; __syncthreads();
    for (int st = 64; st > 0; st >>= 1) {
        if (tid < st) red[tid] += red[tid+st];
        __syncthreads();
    }
    float inv = 1.0f / red[0];
    __syncthreads();

    int d = tid & 63, part = tid >> 6;
    float acc = 0.0f;
    for (int k = part; k <= qi; k += 2)
        acc += s[k] * base[(size_t)k*3*CN + 2*CN + h*HDN + d];
    red[tid] = acc; __syncthreads();
    if (tid < 64) {
        float tot = (red[tid] + red[tid+64]) * inv;
        y[((size_t)(b*TN) + qi)*CN + h*HDN + d] = tot;
    }
}

// ---------------------------------------------------------------------------
// Host orchestration
// ---------------------------------------------------------------------------
extern "C" void kernel_launch(void* const* d_in, const int* in_sizes, int n_in,
                              void* d_out, int out_size) {
    const float* wte    = (const float*)d_in[0];
    const float* wpe    = (const float*)d_in[1];
    const float* ln1_w  = (const float*)d_in[2];
    const float* ln1_b  = (const float*)d_in[3];
    const float* attn_w = (const float*)d_in[4];
    const float* attn_b = (const float*)d_in[5];
    const float* qint_w = (const float*)d_in[6];
    const float* kint_w = (const float*)d_in[7];
    const float* int_bias = (const float*)d_in[8];
    const float* proj_w = (const float*)d_in[9];
    const float* proj_b = (const float*)d_in[10];
    const float* ln2_w  = (const float*)d_in[11];
    const float* ln2_b  = (const float*)d_in[12];
    const float* fc_w   = (const float*)d_in[13];
    const float* fc_b   = (const float*)d_in[14];
    const float* fc2_w  = (const float*)d_in[15];
    const float* fc2_b  = (const float*)d_in[16];
    const float* lnf_w  = (const float*)d_in[17];
    const float* lnf_b  = (const float*)d_in[18];
    const int*   idx    = (const int*)d_in[19];
    float* out = (float*)d_out;

    float *px, *ph, *pqkv, *py, *pqi, *pki, *pp, *pmask, *pfc;
    cudaGetSymbolAddress((void**)&px,    g_x);
    cudaGetSymbolAddress((void**)&ph,    g_h);
    cudaGetSymbolAddress((void**)&pqkv,  g_qkv);
    cudaGetSymbolAddress((void**)&py,    g_y);
    cudaGetSymbolAddress((void**)&pqi,   g_qi);
    cudaGetSymbolAddress((void**)&pki,   g_ki);
    cudaGetSymbolAddress((void**)&pp,    g_p);
    cudaGetSymbolAddress((void**)&pmask, g_mask);
    cudaGetSymbolAddress((void**)&pfc,   g_fc);

    double am1d = 1.000001 - 1.0;
    float am1f = (float)am1d;

    k_embed<<<(MN*CN + 255)/256, 256>>>(wte, wpe, idx, px);
    k_zero<<<1024, 256>>>(pmask, BN*TN*TN);

    for (int l = 0; l < LN; ++l) {
        // --- attention sub-block ---
        k_ln<<<MN, 256>>>(px, ln1_w + l*CN, ln1_b + l*CN, ph);
        k_gemm<<<dim3(MN/128, 3*CN/64), 256>>>(ph, attn_w + (size_t)l*3*CN*CN,
                                               attn_b + l*3*CN, nullptr, pqkv, MN, 3*CN, CN, 0);
        k_gemm<<<dim3(MN/128, DIN/64), 256>>>(ph, qint_w + (size_t)l*DIN*CN,
                                              nullptr, nullptr, pqi, MN, DIN, CN, 0);
        k_gemm<<<dim3(MN/128, DIN/64), 256>>>(ph, kint_w + (size_t)l*DIN*CN,
                                              nullptr, nullptr, pki, MN, DIN, CN, 0);
        // rawT[b][k][q] = kint[b,k,:] . qint[b,q,:]
        for (int b = 0; b < BN; ++b)
            k_gemm<<<dim3(TN/128, TN/64), 256>>>(pki + (size_t)b*TN*DIN, pqi + (size_t)b*TN*DIN,
                                                 nullptr, nullptr, pp + (size_t)b*TN*TN,
                                                 TN, TN, DIN, 0);
        k_entmax<<<(BN*TN*TN + 255)/256, 256>>>(pp, int_bias, l, am1f);
        k_mask<<<BN*TN, 256>>>(pp, pmask);
        k_attn<<<dim3(TN, HN, BN), 128>>>(pqkv, pmask, py);
        k_gemm<<<dim3(MN/128, CN/64), 256>>>(py, proj_w + (size_t)l*CN*CN,
                                             proj_b + l*CN, px, px, MN, CN, CN, 0);
        // --- MLP sub-block (GELU fused into fc epilogue) ---
        k_ln<<<MN, 256>>>(px, ln2_w + l*CN, ln2_b + l*CN, ph);
        k_gemm<<<dim3(MN/128, CFN/64), 256>>>(ph, fc_w + (size_t)l*CFN*CN,
                                              fc_b + l*CFN, nullptr, pfc, MN, CFN, CN, 1);
        k_gemm<<<dim3(MN/128, CN/64), 256>>>(pfc, fc2_w + (size_t)l*CN*CFN,
                                             fc2_b + l*CN, px, px, MN, CN, CFN, 0);
    }

    k_ln<<<MN, 256>>>(px, lnf_w, lnf_b, ph);
    k_gemm<<<dim3(MN/128, VN/64), 256>>>(ph, wte, nullptr, nullptr, out, MN, VN, CN, 0);
}